// round 13
// baseline (speedup 1.0000x reference)
#include <cuda_runtime.h>
#include <math.h>
#include <stdint.h>

#define NB 2
#define NTOK 4096

__device__ float g_Pqc[8192*512];
__device__ float g_Pqs[8192*512];
__device__ float g_Pkc[8192*512];
__device__ float g_Pvc[8192*512];
__device__ uint32_t g_PksU[8192*256];   // K_s as bf16x2 pairs, slot-permuted
__device__ float g_Pvs[8192*128];       // V_s fp32 (unrounded)
__device__ uint32_t g_Vp[16*2048*16];   // V_s as bf16x2 key-pairs
__device__ float g_Vcs[16*16];          // V_s column sums per (b,h)
__device__ float g_Sca[16*16*64*64];
__device__ float g_Pca[16*64*64];
// tf32-rounded inputs, k-columns PAIR-PERMUTED within 8-groups: [c0,c4,c1,c5,c2,c6,c3,c7]
__device__ float g_ts [8192*512];
__device__ float g_tsh[8192*512];
__device__ float g_th [8192*128];
__device__ float g_tWqc[512*512];
__device__ float g_tWqs[512*512];
__device__ float g_tWkc[512*512];
__device__ float g_tWvc[512*512];
__device__ float g_tWks[512*512];
__device__ float g_tWvs[128*128];

// =================== helpers ===================
__device__ __forceinline__ uint32_t f2tf(float x) {
    uint32_t r; asm("cvt.rna.tf32.f32 %0, %1;" : "=r"(r) : "f"(x)); return r;
}
__device__ __forceinline__ uint32_t f2bf2(float lo, float hi) {
    uint32_t r; asm("cvt.rn.bf16x2.f32 %0, %1, %2;" : "=r"(r) : "f"(hi), "f"(lo)); return r;
}
__device__ __forceinline__ float ex2f(float x) {
    float r; asm("ex2.approx.ftz.f32 %0, %1;" : "=f"(r) : "f"(x)); return r;
}
__device__ __forceinline__ void mma8(float* d, const uint32_t* a, uint32_t b0, uint32_t b1) {
    asm volatile(
        "mma.sync.aligned.m16n8k8.row.col.f32.tf32.tf32.f32 "
        "{%0,%1,%2,%3},{%4,%5,%6,%7},{%8,%9},{%0,%1,%2,%3};"
        : "+f"(d[0]), "+f"(d[1]), "+f"(d[2]), "+f"(d[3])
        : "r"(a[0]), "r"(a[1]), "r"(a[2]), "r"(a[3]), "r"(b0), "r"(b1));
}
__device__ __forceinline__ void mma16bf(float* d, const uint32_t* a, uint32_t b0, uint32_t b1) {
    asm volatile(
        "mma.sync.aligned.m16n8k16.row.col.f32.bf16.bf16.f32 "
        "{%0,%1,%2,%3},{%4,%5,%6,%7},{%8,%9},{%0,%1,%2,%3};"
        : "+f"(d[0]), "+f"(d[1]), "+f"(d[2]), "+f"(d[3])
        : "r"(a[0]), "r"(a[1]), "r"(a[2]), "r"(a[3]), "r"(b0), "r"(b1));
}
__device__ __forceinline__ uint32_t smem_u32(const void* p) {
    uint32_t a;
    asm("{ .reg .u64 t; cvta.to.shared.u64 t, %1; cvt.u32.u64 %0, t; }" : "=r"(a) : "l"(p));
    return a;
}
__device__ __forceinline__ void cpasync16(uint32_t dst, const void* src) {
    asm volatile("cp.async.ca.shared.global [%0], [%1], 16;" :: "r"(dst), "l"(src));
}
#define CP_COMMIT() asm volatile("cp.async.commit_group;" ::: "memory")
#define CP_WAIT2()  asm volatile("cp.async.wait_group 2;" ::: "memory")
#define CP_WAIT1()  asm volatile("cp.async.wait_group 1;" ::: "memory")
#define CP_WAIT0()  asm volatile("cp.async.wait_group 0;" ::: "memory")

// ======= prep: tf32-round + pair-permute k-columns (units of 8 floats) =======
#define SEG0 524288
#define SEG1 1048576
#define SEG2 1179648
#define SEG3 1212416
#define SEG4 1245184
#define SEG5 1277952
#define SEG6 1310720
#define SEG7 1343488
#define SEGT 1345536
__global__ __launch_bounds__(256) void prep(
    const float4* __restrict__ s, const float4* __restrict__ sh, const float4* __restrict__ h,
    const float4* __restrict__ wqc, const float4* __restrict__ wqs, const float4* __restrict__ wkc,
    const float4* __restrict__ wvc, const float4* __restrict__ wks, const float4* __restrict__ wvs)
{
    int i = blockIdx.x * blockDim.x + threadIdx.x;
    if (i >= SEGT) return;
    const float4* src; float4* dst; int off;
    if      (i < SEG0) { src = s;   dst = (float4*)g_ts;   off = i; }
    else if (i < SEG1) { src = sh;  dst = (float4*)g_tsh;  off = i - SEG0; }
    else if (i < SEG2) { src = h;   dst = (float4*)g_th;   off = i - SEG1; }
    else if (i < SEG3) { src = wqc; dst = (float4*)g_tWqc; off = i - SEG2; }
    else if (i < SEG4) { src = wqs; dst = (float4*)g_tWqs; off = i - SEG3; }
    else if (i < SEG5) { src = wkc; dst = (float4*)g_tWkc; off = i - SEG4; }
    else if (i < SEG6) { src = wvc; dst = (float4*)g_tWvc; off = i - SEG5; }
    else if (i < SEG7) { src = wks; dst = (float4*)g_tWks; off = i - SEG6; }
    else               { src = wvs; dst = (float4*)g_tWvs; off = i - SEG7; }
    float4 a = src[2*off], b = src[2*off + 1];
    float c0 = __uint_as_float(f2tf(a.x)), c1 = __uint_as_float(f2tf(a.y));
    float c2 = __uint_as_float(f2tf(a.z)), c3 = __uint_as_float(f2tf(a.w));
    float c4 = __uint_as_float(f2tf(b.x)), c5 = __uint_as_float(f2tf(b.y));
    float c6 = __uint_as_float(f2tf(b.z)), c7 = __uint_as_float(f2tf(b.w));
    dst[2*off]     = make_float4(c0, c4, c1, c5);
    dst[2*off + 1] = make_float4(c2, c6, c3, c7);
}

// ====== tf32 TC GEMM, 4-stage cp.async, pair-permuted fragments (LDS.64) ======
#define GSTG 2560
#define GSMEM (4*GSTG*2*4)   // 81920 bytes

// mode: 0 = plain fp32 out, 2 = bf16x2 pair-permuted out (K_s)
template<int K, int O>
__device__ __forceinline__ void gemm_tc_tile(const float* __restrict__ A,
                                             const float* __restrict__ W,
                                             float* __restrict__ C,
                                             int m0, int o0, int mode,
                                             float* dynsm)
{
    const int NC = K / 16;
    float* sA = dynsm;
    float* sW = dynsm + 4*GSTG;
    int tid = threadIdx.x, w = tid >> 5, lane = tid & 31;
    int g = lane >> 2, tg = lane & 3;
    int wm = w >> 2, wn = w & 3;
    int pr = tid >> 1, pc = (tid & 1) << 3;
    const float* Ap = A + (size_t)(m0 + pr) * K + pc;
    const float* Wp = W + (size_t)(o0 + pr) * K + pc;
    uint32_t sAb[4], sWb[4];
    #pragma unroll
    for (int st = 0; st < 4; st++) {
        sAb[st] = smem_u32(sA + st*GSTG + pr*20 + pc);
        sWb[st] = smem_u32(sW + st*GSTG + pr*20 + pc);
    }

    float acc[4][4][4];
    #pragma unroll
    for (int mt = 0; mt < 4; mt++)
        #pragma unroll
        for (int nt = 0; nt < 4; nt++)
            #pragma unroll
            for (int e = 0; e < 4; e++) acc[mt][nt][e] = 0.f;

    // prologue: chunks 0..2 -> stages 0..2
    #pragma unroll
    for (int p = 0; p < 3; p++) {
        cpasync16(sAb[p],      Ap + p*16); cpasync16(sAb[p] + 16, Ap + p*16 + 4);
        cpasync16(sWb[p],      Wp + p*16); cpasync16(sWb[p] + 16, Wp + p*16 + 4);
        CP_COMMIT();
    }

    #pragma unroll 1
    for (int c = 0; c < NC; c++) {
        if (c <= NC - 3)      { CP_WAIT2(); }
        else if (c == NC - 2) { CP_WAIT1(); }
        else                  { CP_WAIT0(); }
        __syncthreads();
        if (c + 3 < NC) {
            int st = (c + 3) & 3;
            const float* ap = Ap + (c+3)*16;
            const float* wp = Wp + (c+3)*16;
            cpasync16(sAb[st],      ap); cpasync16(sAb[st] + 16, ap + 4);
            cpasync16(sWb[st],      wp); cpasync16(sWb[st] + 16, wp + 4);
            CP_COMMIT();
        }
        int st = c & 3;
        const uint32_t* cA = (const uint32_t*)(sA + st*GSTG);
        const uint32_t* cW = (const uint32_t*)(sW + st*GSTG);
        #pragma unroll
        for (int ks = 0; ks < 2; ks++) {
            uint32_t af[4][4], bf[4][2];
            #pragma unroll
            for (int mt = 0; mt < 4; mt++) {
                int rb = wm*64 + mt*16;
                uint2 p0 = *(const uint2*)&cA[(rb+g  )*20 + ks*8 + 2*tg];  // (col tg, col tg+4)
                uint2 p1 = *(const uint2*)&cA[(rb+g+8)*20 + ks*8 + 2*tg];
                af[mt][0] = p0.x; af[mt][1] = p1.x; af[mt][2] = p0.y; af[mt][3] = p1.y;
            }
            #pragma unroll
            for (int nt = 0; nt < 4; nt++) {
                int rb = wn*32 + nt*8 + g;
                uint2 pb = *(const uint2*)&cW[rb*20 + ks*8 + 2*tg];
                bf[nt][0] = pb.x; bf[nt][1] = pb.y;
            }
            #pragma unroll
            for (int mt = 0; mt < 4; mt++)
                #pragma unroll
                for (int nt = 0; nt < 4; nt++)
                    mma8(acc[mt][nt], af[mt], bf[nt][0], bf[nt][1]);
        }
    }
    #pragma unroll
    for (int mt = 0; mt < 4; mt++) {
        int r = m0 + wm*64 + mt*16 + g;
        #pragma unroll
        for (int nt = 0; nt < 4; nt++) {
            float v0 = acc[mt][nt][0], v1 = acc[mt][nt][1];
            float v2 = acc[mt][nt][2], v3 = acc[mt][nt][3];
            if (mode == 2) {
                uint32_t lo = f2bf2(v0, v1);
                uint32_t hi = f2bf2(v2, v3);
                int c0  = o0 + wn*32 + nt*8 + 2*tg;
                int blk = c0 >> 6;
                int d   = c0 & 63;
                int slot = (nt & 1) ? (2*tg + 1) : (2*tg);
                uint32_t* kp = g_PksU + (size_t)r*256 + blk*32 + (d >> 4)*8 + slot;
                kp[0]     = lo;
                kp[8*256] = hi;
            } else {
                float* cp = C + (size_t)r*O + o0 + wn*32 + nt*8;
                *(float2*)(cp + 2*tg)       = make_float2(v0, v1);
                *(float2*)(cp + 8*O + 2*tg) = make_float2(v2, v3);
            }
        }
    }
}

__global__ __launch_bounds__(256, 2) void gemm_proj_tc()
{
    extern __shared__ float gdsm[];
    int job = blockIdx.x >> 2;
    int ot  = blockIdx.x & 3;
    int m0  = blockIdx.y << 7;
    const float* A; const float* W; float* C; int mode;
    switch (job) {
        case 0: A = g_tsh; W = g_tWqs; C = g_Pqs; mode = 0; break;
        case 1: A = g_tsh; W = g_tWkc; C = g_Pkc; mode = 0; break;
        case 2: A = g_tsh; W = g_tWvc; C = g_Pvc; mode = 0; break;
        case 3: A = g_tsh; W = g_tWks; C = (float*)g_PksU; mode = 2; break;
        default: A = g_ts; W = g_tWqc; C = g_Pqc; mode = 0; break;
    }
    gemm_tc_tile<512,512>(A, W, C, m0, ot << 7, mode, gdsm);
}

__global__ __launch_bounds__(256, 2) void gemm_vs_tc()
{
    extern __shared__ float gdsm[];
    gemm_tc_tile<128,128>(g_th, g_tWvs, g_Pvs, blockIdx.x << 7, 0, 0, gdsm);
}

// ============ repack V_s to bf16 key-pairs + fp32 column sums ============
__global__ __launch_bounds__(256) void repack_v()
{
    __shared__ float4 red[256];
    int bh = blockIdx.x;
    int b = bh >> 3, h = bh & 7;
    const float* Vb = g_Pvs + ((size_t)b*NTOK + h*512)*128;
    uint32_t* Vp = g_Vp + (size_t)bh*32768;
    int tid = threadIdx.x;
    float4 part = make_float4(0.f, 0.f, 0.f, 0.f);
    #pragma unroll 4
    for (int i = tid; i < 8192; i += 256) {
        int key2 = i >> 2, cg = (i & 3) << 2;
        float4 v0 = *(const float4*)(Vb + (size_t)(2*key2)*16 + cg);
        float4 v1 = *(const float4*)(Vb + (size_t)(2*key2+1)*16 + cg);
        uint4 pk;
        pk.x = f2bf2(v0.x, v1.x);
        pk.y = f2bf2(v0.y, v1.y);
        pk.z = f2bf2(v0.z, v1.z);
        pk.w = f2bf2(v0.w, v1.w);
        *(uint4*)(Vp + (size_t)key2*16 + cg) = pk;
        part.x += v0.x + v1.x;
        part.y += v0.y + v1.y;
        part.z += v0.z + v1.z;
        part.w += v0.w + v1.w;
    }
    red[tid] = part;
    __syncthreads();
    if (tid < 4) {
        float4 ssum = make_float4(0.f, 0.f, 0.f, 0.f);
        for (int t = tid; t < 256; t += 4) {
            float4 v = red[t];
            ssum.x += v.x; ssum.y += v.y; ssum.z += v.z; ssum.w += v.w;
        }
        *(float4*)(g_Vcs + bh*16 + tid*4) = ssum;
    }
}

// =================== channel attention (fp32, unchanged) ===================
__global__ __launch_bounds__(256) void ca_scores()
{
    __shared__ float Qs[32][68];
    __shared__ float Ks[32][68];
    int slice = blockIdx.x;
    int bh    = blockIdx.y;
    int b = bh >> 3, h = bh & 7;
    const float* Qc = g_Pqc + ((size_t)b*NTOK + h*512) * 512;
    const float* Kc = g_Pkc + ((size_t)b*NTOK + h*512) * 512;
    int tid = threadIdx.x;
    int lr = tid >> 3, lc = (tid & 7) << 3;
    int i0 = (tid >> 4) << 2, j0 = (tid & 15) << 2;
    float acc[4][4];
    #pragma unroll
    for (int i = 0; i < 4; i++)
        #pragma unroll
        for (int j = 0; j < 4; j++) acc[i][j] = 0.f;
    #pragma unroll 1
    for (int nt = 0; nt < 8; nt++) {
        int nb = slice*256 + (nt << 5);
        const float* qp = Qc + (size_t)(nb + lr)*64 + lc;
        const float* kp = Kc + (size_t)(nb + lr)*64 + lc;
        float4 q0 = *(const float4*)qp, q1 = *(const float4*)(qp+4);
        float4 k0 = *(const float4*)kp, k1 = *(const float4*)(kp+4);
        __syncthreads();
        *(float4*)&Qs[lr][lc] = q0; *(float4*)&Qs[lr][lc+4] = q1;
        *(float4*)&Ks[lr][lc] = k0; *(float4*)&Ks[lr][lc+4] = k1;
        __syncthreads();
        #pragma unroll 8
        for (int nn = 0; nn < 32; nn++) {
            float4 q = *(const float4*)&Qs[nn][i0];
            float4 k = *(const float4*)&Ks[nn][j0];
            float qa[4] = {q.x,q.y,q.z,q.w};
            float ka[4] = {k.x,k.y,k.z,k.w};
            #pragma unroll
            for (int i = 0; i < 4; i++)
                #pragma unroll
                for (int j = 0; j < 4; j++)
                    acc[i][j] = fmaf(qa[i], ka[j], acc[i][j]);
        }
    }
    float* dst = g_Sca + ((size_t)(bh*16 + slice)*64)*64;
    #pragma unroll
    for (int i = 0; i < 4; i++)
        *(float4*)&dst[(i0+i)*64 + j0] = make_float4(acc[i][0],acc[i][1],acc[i][2],acc[i][3]);
}

__global__ void ca_reduce(const float* __restrict__ temp)
{
    int bh = blockIdx.x;
    int h  = bh & 7;
    int i  = threadIdx.x;
    float scale = 0.125f * temp[h];
    float row[64];
    #pragma unroll
    for (int j = 0; j < 64; j++) {
        float s = 0.f;
        #pragma unroll
        for (int p = 0; p < 16; p++)
            s += g_Sca[((size_t)(bh*16+p)*64 + i)*64 + j];
        row[j] = s * scale;
    }
    float m = row[0];
    #pragma unroll
    for (int j = 1; j < 64; j++) m = fmaxf(m, row[j]);
    float sum = 0.f;
    #pragma unroll
    for (int j = 0; j < 64; j++) { row[j] = __expf(row[j]-m); sum += row[j]; }
    float inv = 1.f / sum;
    #pragma unroll
    for (int j = 0; j < 64; j++)
        g_Pca[((size_t)bh*64 + i)*64 + j] = row[j]*inv;
}

__global__ __launch_bounds__(256) void ca_out(float* __restrict__ out)
{
    __shared__ float Pts[64][68];
    __shared__ float Vt[64][68];
    int mt = blockIdx.x;
    int bh = blockIdx.y;
    int b = bh >> 3, h = bh & 7;
    int tid = threadIdx.x;
    {
        int i  = tid & 63;
        int jc = (tid >> 6) << 4;
        const float* pp = g_Pca + ((size_t)bh*64 + i)*64 + jc;
        #pragma unroll
        for (int t = 0; t < 4; t++) {
            float4 v = *(const float4*)(pp + t*4);
            Pts[jc+t*4+0][i] = v.x; Pts[jc+t*4+1][i] = v.y;
            Pts[jc+t*4+2][i] = v.z; Pts[jc+t*4+3][i] = v.w;
        }
    }
    {
        int mm = tid & 63;
        int jc = (tid >> 6) << 4;
        const float* vp = g_Pvc + ((size_t)b*NTOK + h*512)*512 + (size_t)(mt*64 + mm)*64 + jc;
        #pragma unroll
        for (int t = 0; t < 4; t++) {
            float4 v = *(const float4*)(vp + t*4);
            Vt[jc+t*4+0][mm] = v.x; Vt[jc+t*4+1][mm] = v.y;
            Vt[jc+t*4+2][mm] = v.z; Vt[jc+t*4+3][mm] = v.w;
        }
    }
    __syncthreads();
    int i0 = (tid >> 4) << 2, m0 = (tid & 15) << 2;
    float acc[4][4];
    #pragma unroll
    for (int i = 0; i < 4; i++)
        #pragma unroll
        for (int j = 0; j < 4; j++) acc[i][j] = 0.f;
    #pragma unroll 8
    for (int j = 0; j < 64; j++) {
        float4 p = *(const float4*)&Pts[j][i0];
        float4 v = *(const float4*)&Vt[j][m0];
        float pa[4] = {p.x,p.y,p.z,p.w};
        float va[4] = {v.x,v.y,v.z,v.w};
        #pragma unroll
        for (int i = 0; i < 4; i++)
            #pragma unroll
            for (int m = 0; m < 4; m++)
                acc[i][m] = fmaf(pa[i], va[m], acc[i][m]);
    }
    int rowoff  = mt >> 3;
    int colbase = (mt & 7)*64 + m0;
    #pragma unroll
    for (int i = 0; i < 4; i++) {
        int row = h*512 + (i0+i)*8 + rowoff;
        float* op = out + ((size_t)b*NTOK + row)*640 + colbase;
        *(float4*)op = make_float4(acc[i][0],acc[i][1],acc[i][2],acc[i][3]);
    }
}

// ====== spatial flash: all-bf16 mma, 1+u softmax decomposition (R11) ======
#define KSTRU 40
#define FKOFFU(s) ((s)*2560)
#define FVOFFU(s) (7680 + (s)*768)
#define FSMEM (9984 * 4)

__global__ __launch_bounds__(256, 2) void flash_mma(const float* __restrict__ t2,
                                                    float* __restrict__ out)
{
    extern __shared__ float sm[];
    uint32_t* smu = (uint32_t*)sm;
    int tid = threadIdx.x, w = tid >> 5, lane = tid & 31;
    int g = lane >> 2, tg = lane & 3;
    int qt = blockIdx.x, bh = blockIdx.y;
    int b = bh >> 3, h = bh & 7;
    const float*    Qb  = g_Pqs  + ((size_t)b*NTOK + h*512)*512;
    const uint32_t* KbU = g_PksU + ((size_t)b*NTOK + h*512)*256;
    const uint32_t* Vpg = g_Vp + (size_t)bh*32768;
    float qscale = 0.125f * t2[h] * 1.4426950408889634f;

    int kr = tid >> 2, kq = tid & 3;
    uint32_t kdst[3], vdst[3];
    #pragma unroll
    for (int st = 0; st < 3; st++) {
        kdst[st] = smem_u32(smu + FKOFFU(st) + kr*KSTRU + kq*8);
        vdst[st] = smem_u32(smu + FVOFFU(st) + kr*24 + kq*4);
    }
    const uint32_t* ksrc = KbU + (size_t)kr*32 + kq*8;
    const uint32_t* vsrc = Vpg + (size_t)kr*16 + kq*4;

    int q0 = w << 4;
    uint32_t qa[4][4];
    {
        const float* qr0 = Qb + (size_t)(qt*128 + q0 + g)*64;
        const float* qr1 = qr0 + 8*64;
        #pragma unroll
        for (int kd = 0; kd < 4; kd++) {
            int d0 = kd*16 + 2*tg;
            qa[kd][0] = f2bf2(qr0[d0]*qscale,   qr0[d0+1]*qscale);
            qa[kd][1] = f2bf2(qr1[d0]*qscale,   qr1[d0+1]*qscale);
            qa[kd][2] = f2bf2(qr0[d0+8]*qscale, qr0[d0+9]*qscale);
            qa[kd][3] = f2bf2(qr1[d0+8]*qscale, qr1[d0+9]*qscale);
        }
    }

    float Ofr[2][4];
    #pragma unroll
    for (int n = 0; n < 2; n++)
        #pragma unroll
        for (int e = 0; e < 4; e++) Ofr[n][e] = 0.f;
    float l0 = 0.f, l1 = 0.f;

    cpasync16(kdst[0], ksrc); cpasync16(kdst[0] + 16, ksrc + 4);
    if (tid < 128) cpasync16(vdst[0], vsrc);
    CP_COMMIT();
    cpasync16(kdst[1], ksrc + 2048); cpasync16(kdst[1] + 16, ksrc + 2052);
    if (tid < 128) cpasync16(vdst[1], vsrc + 512);
    CP_COMMIT();

    #pragma unroll 1
    for (int c = 0; c < 64; c++) {
        if (c + 1 < 64) { CP_WAIT1(); } else { CP_WAIT0(); }
        __syncthreads();
        if (c + 2 < 64) {
            int st = (c + 2) % 3;
            const uint32_t* kp = ksrc + (size_t)(c+2)*2048;
            const uint32_t* vp = vsrc + (size_t)(c+2)*512;
            cpasync16(kdst[st], kp); cpasync16(kdst[st] + 16, kp + 4);
            if (tid < 128) cpasync16(vdst[st], vp);
            CP_COMMIT();
        }
        int st = c % 3;
        const uint32_t* Kc = smu + FKOFFU(st);
        const uint32_t* Vc = smu + FVOFFU(st);

        #pragma unroll
        for (int ks = 0; ks < 4; ks++) {
            float s0[4] = {0.f,0.f,0.f,0.f};
            float s1[4] = {0.f,0.f,0.f,0.f};
            const uint32_t* kr0 = Kc + (ks*16 + g)*KSTRU;
            const uint32_t* kr1 = kr0 + 8*KSTRU;
            #pragma unroll
            for (int kd = 0; kd < 4; kd++) {
                uint2 k0 = *(const uint2*)(kr0 + kd*8 + 2*tg);
                uint2 k1 = *(const uint2*)(kr1 + kd*8 + 2*tg);
                mma16bf(s0, qa[kd], k0.x, k0.y);
                mma16bf(s1, qa[kd], k1.x, k1.y);
            }
            float u00 = ex2f(s0[0]) - 1.f, u01 = ex2f(s0[1]) - 1.f;
            float u02 = ex2f(s0[2]) - 1.f, u03 = ex2f(s0[3]) - 1.f;
            float u10 = ex2f(s1[0]) - 1.f, u11 = ex2f(s1[1]) - 1.f;
            float u12 = ex2f(s1[2]) - 1.f, u13 = ex2f(s1[3]) - 1.f;
            l0 += (u00 + u01) + (u10 + u11);
            l1 += (u02 + u03) + (u12 + u13);
            uint32_t ap[4];
            ap[0] = f2bf2(u00, u01);
            ap[1] = f2bf2(u02, u03);
            ap[2] = f2bf2(u10, u11);
            ap[3] = f2bf2(u12, u13);
            const uint32_t* vr0 = Vc + (ks*8 + tg)*24;
            const uint32_t* vr1 = Vc + (ks*8 + tg + 4)*24;
            mma16bf(Ofr[0], ap, vr0[g],     vr1[g]);
            mma16bf(Ofr[1], ap, vr0[g + 8], vr1[g + 8]);
        }
    }
    l0 += __shfl_xor_sync(0xffffffffu, l0, 1);
    l0 += __shfl_xor_sync(0xffffffffu, l0, 2);
    l1 += __shfl_xor_sync(0xffffffffu, l1, 1);
    l1 += __shfl_xor_sync(0xffffffffu, l1, 2);

    float inv0 = 1.f / (4096.f + l0), inv1 = 1.f / (4096.f + l1);
    int n_g  = qt*128 + q0 + g;
    int n_g8 = n_g + 8;
    float* op0 = out + ((size_t)b*NTOK + h*512 + (n_g  >> 3))*640 + 512 + (n_g  & 7)*16;
    float* op1 = out + ((size_t)b*NTOK + h*512 + (n_g8 >> 3))*640 + 512 + (n_g8 & 7)*16;
    #pragma unroll
    for (int nt = 0; nt < 2; nt++) {
        int cbase = nt*8 + 2*tg;
        float2 cs = *(const float2*)(g_Vcs + bh*16 + cbase);
        float2 a, c2;
        a.x  = (cs.x + Ofr[nt][0])*inv0; a.y  = (cs.y + Ofr[nt][1])*inv0;
        c2.x = (cs.x + Ofr[nt][2])*inv1; c2.y = (cs.y + Ofr[nt][3])*inv1;
        *(float2*)(op0 + cbase) = a;
        *(float2*)(op1 + cbase) = c2;
    }
}

// =================== launch (sequential, R11 order) ===================
extern "C" void kernel_launch(void* const* d_in, const int* in_sizes, int n_in,
                              void* d_out, int out_size)
{
    const float* s_in = (const float*)d_in[0];
    const float* h_in = (const float*)d_in[1];
    const float* sh   = (const float*)d_in[2];
    const float* t1   = (const float*)d_in[3];
    const float* t2   = (const float*)d_in[4];
    const float* Wqc  = (const float*)d_in[5];
    const float* Wqs  = (const float*)d_in[6];
    const float* Wkc  = (const float*)d_in[7];
    const float* Wvc  = (const float*)d_in[8];
    const float* Wks  = (const float*)d_in[9];
    const float* Wvs  = (const float*)d_in[10];
    float* out = (float*)d_out;

    cudaFuncSetAttribute(flash_mma, cudaFuncAttributeMaxDynamicSharedMemorySize, FSMEM);
    cudaFuncSetAttribute(gemm_proj_tc, cudaFuncAttributeMaxDynamicSharedMemorySize, GSMEM);
    cudaFuncSetAttribute(gemm_vs_tc, cudaFuncAttributeMaxDynamicSharedMemorySize, GSMEM);

    prep<<<(SEGT + 255) / 256, 256>>>(
        (const float4*)s_in, (const float4*)sh, (const float4*)h_in,
        (const float4*)Wqc, (const float4*)Wqs, (const float4*)Wkc,
        (const float4*)Wvc, (const float4*)Wks, (const float4*)Wvs);
    gemm_proj_tc<<<dim3(20,64), 256, GSMEM>>>();
    gemm_vs_tc<<<64, 256, GSMEM>>>();
    repack_v<<<16, 256>>>();
    flash_mma<<<dim3(32,16), 256, FSMEM>>>(t2, out);
    ca_scores<<<dim3(16,16), 256>>>();
    ca_reduce<<<16, 64>>>(t1);
    ca_out<<<dim3(64,16), 256>>>(out);
}

// round 14
// speedup vs baseline: 1.0318x; 1.0318x over previous
#include <cuda_runtime.h>
#include <math.h>
#include <stdint.h>

#define NB 2
#define NTOK 4096

__device__ float g_Pqc[8192*512];
__device__ float g_Pqs[8192*512];
__device__ float g_Pkc[8192*512];
__device__ float g_Pvc[8192*512];
__device__ uint32_t g_PksU[8192*256];   // K_s as bf16x2 pairs, slot-permuted
__device__ float g_Pvs[8192*128];       // V_s fp32 (unrounded)
__device__ uint32_t g_Vp[16*2048*16];   // V_s as bf16x2 key-pairs
__device__ float g_Vcs[16*16];          // V_s column sums per (b,h)
__device__ float g_VcsP[128*16];        // partial column sums
__device__ float g_Sca[16*16*64*64];
__device__ float g_Pca[16*64*64];
__device__ float g_ts [8192*512];
__device__ float g_tsh[8192*512];
__device__ float g_th [8192*128];
__device__ float g_tWqc[512*512];
__device__ float g_tWqs[512*512];
__device__ float g_tWkc[512*512];
__device__ float g_tWvc[512*512];
__device__ float g_tWks[512*512];
__device__ float g_tWvs[128*128];

// =================== helpers ===================
__device__ __forceinline__ uint32_t f2tf(float x) {
    uint32_t r; asm("cvt.rna.tf32.f32 %0, %1;" : "=r"(r) : "f"(x)); return r;
}
__device__ __forceinline__ uint32_t f2bf2(float lo, float hi) {
    uint32_t r; asm("cvt.rn.bf16x2.f32 %0, %1, %2;" : "=r"(r) : "f"(hi), "f"(lo)); return r;
}
__device__ __forceinline__ float ex2f(float x) {
    float r; asm("ex2.approx.ftz.f32 %0, %1;" : "=f"(r) : "f"(x)); return r;
}
__device__ __forceinline__ void mma8(float* d, const uint32_t* a, uint32_t b0, uint32_t b1) {
    asm volatile(
        "mma.sync.aligned.m16n8k8.row.col.f32.tf32.tf32.f32 "
        "{%0,%1,%2,%3},{%4,%5,%6,%7},{%8,%9},{%0,%1,%2,%3};"
        : "+f"(d[0]), "+f"(d[1]), "+f"(d[2]), "+f"(d[3])
        : "r"(a[0]), "r"(a[1]), "r"(a[2]), "r"(a[3]), "r"(b0), "r"(b1));
}
__device__ __forceinline__ void mma16bf(float* d, const uint32_t* a, uint32_t b0, uint32_t b1) {
    asm volatile(
        "mma.sync.aligned.m16n8k16.row.col.f32.bf16.bf16.f32 "
        "{%0,%1,%2,%3},{%4,%5,%6,%7},{%8,%9},{%0,%1,%2,%3};"
        : "+f"(d[0]), "+f"(d[1]), "+f"(d[2]), "+f"(d[3])
        : "r"(a[0]), "r"(a[1]), "r"(a[2]), "r"(a[3]), "r"(b0), "r"(b1));
}
__device__ __forceinline__ uint32_t smem_u32(const void* p) {
    uint32_t a;
    asm("{ .reg .u64 t; cvta.to.shared.u64 t, %1; cvt.u32.u64 %0, t; }" : "=r"(a) : "l"(p));
    return a;
}
__device__ __forceinline__ void cpasync16(uint32_t dst, const void* src) {
    asm volatile("cp.async.ca.shared.global [%0], [%1], 16;" :: "r"(dst), "l"(src));
}
#define CP_COMMIT() asm volatile("cp.async.commit_group;" ::: "memory")
#define CP_WAIT1()  asm volatile("cp.async.wait_group 1;" ::: "memory")
#define CP_WAIT0()  asm volatile("cp.async.wait_group 0;" ::: "memory")

// =================== prep: round all inputs to tf32 once (R11) ===================
#define SEG0 1048576
#define SEG1 2097152
#define SEG2 2359296
#define SEG3 2424832
#define SEG4 2490368
#define SEG5 2555904
#define SEG6 2621440
#define SEG7 2686976
#define SEGT 2691072
__global__ __launch_bounds__(256) void prep(
    const float4* __restrict__ s, const float4* __restrict__ sh, const float4* __restrict__ h,
    const float4* __restrict__ wqc, const float4* __restrict__ wqs, const float4* __restrict__ wkc,
    const float4* __restrict__ wvc, const float4* __restrict__ wks, const float4* __restrict__ wvs)
{
    int i = blockIdx.x * blockDim.x + threadIdx.x;
    if (i >= SEGT) return;
    const float4* src; float4* dst; int off;
    if      (i < SEG0) { src = s;   dst = (float4*)g_ts;   off = i; }
    else if (i < SEG1) { src = sh;  dst = (float4*)g_tsh;  off = i - SEG0; }
    else if (i < SEG2) { src = h;   dst = (float4*)g_th;   off = i - SEG1; }
    else if (i < SEG3) { src = wqc; dst = (float4*)g_tWqc; off = i - SEG2; }
    else if (i < SEG4) { src = wqs; dst = (float4*)g_tWqs; off = i - SEG3; }
    else if (i < SEG5) { src = wkc; dst = (float4*)g_tWkc; off = i - SEG4; }
    else if (i < SEG6) { src = wvc; dst = (float4*)g_tWvc; off = i - SEG5; }
    else if (i < SEG7) { src = wks; dst = (float4*)g_tWks; off = i - SEG6; }
    else               { src = wvs; dst = (float4*)g_tWvs; off = i - SEG7; }
    float4 v = src[off];
    dst[off] = make_float4(__uint_as_float(f2tf(v.x)), __uint_as_float(f2tf(v.y)),
                           __uint_as_float(f2tf(v.z)), __uint_as_float(f2tf(v.w)));
}

// ====== tf32 TC GEMM: K-chunk 32, 3-stage cp.async, conflict-free scalar LDS ======
#define GSTG 4608              // floats per stage: 128 rows x 36
#define GSMEM (3*GSTG*2*4)     // 110592 bytes

// mode: 0 = plain fp32 out, 2 = bf16x2 pair-permuted out (K_s)
template<int K, int O>
__device__ __forceinline__ void gemm_tc_tile(const float* __restrict__ A,
                                             const float* __restrict__ W,
                                             float* __restrict__ C,
                                             int m0, int o0, int mode,
                                             float* dynsm)
{
    const int NC = K / 32;
    float* sA = dynsm;
    float* sW = dynsm + 3*GSTG;
    int tid = threadIdx.x, w = tid >> 5, lane = tid & 31;
    int g = lane >> 2, tg = lane & 3;
    int wm = w >> 2, wn = w & 3;
    int pr = tid >> 1, pc = (tid & 1) << 4;   // copy: row pr, 16 floats at pc
    const float* Ap = A + (size_t)(m0 + pr) * K + pc;
    const float* Wp = W + (size_t)(o0 + pr) * K + pc;
    uint32_t sAb[3], sWb[3];
    #pragma unroll
    for (int st = 0; st < 3; st++) {
        sAb[st] = smem_u32(sA + st*GSTG + pr*36 + pc);
        sWb[st] = smem_u32(sW + st*GSTG + pr*36 + pc);
    }

    float acc[4][4][4];
    #pragma unroll
    for (int mt = 0; mt < 4; mt++)
        #pragma unroll
        for (int nt = 0; nt < 4; nt++)
            #pragma unroll
            for (int e = 0; e < 4; e++) acc[mt][nt][e] = 0.f;

    // prologue: chunks 0,1 -> stages 0,1
    #pragma unroll
    for (int p = 0; p < 2; p++) {
        #pragma unroll
        for (int j = 0; j < 4; j++) {
            cpasync16(sAb[p] + j*16, Ap + p*32 + j*4);
            cpasync16(sWb[p] + j*16, Wp + p*32 + j*4);
        }
        CP_COMMIT();
    }

    #pragma unroll 1
    for (int c = 0; c < NC; c++) {
        if (c + 1 < NC) { CP_WAIT1(); } else { CP_WAIT0(); }
        __syncthreads();
        if (c + 2 < NC) {
            int st = (c + 2) % 3;
            const float* ap = Ap + (c+2)*32;
            const float* wp = Wp + (c+2)*32;
            #pragma unroll
            for (int j = 0; j < 4; j++) {
                cpasync16(sAb[st] + j*16, ap + j*4);
                cpasync16(sWb[st] + j*16, wp + j*4);
            }
            CP_COMMIT();
        }
        int st = c % 3;
        const uint32_t* cA = (const uint32_t*)(sA + st*GSTG);
        const uint32_t* cW = (const uint32_t*)(sW + st*GSTG);
        #pragma unroll
        for (int ks = 0; ks < 4; ks++) {
            uint32_t af[4][4], bf[4][2];
            #pragma unroll
            for (int mt = 0; mt < 4; mt++) {
                int rb = wm*64 + mt*16;
                af[mt][0] = cA[(rb+g  )*36 + ks*8 + tg];
                af[mt][1] = cA[(rb+g+8)*36 + ks*8 + tg];
                af[mt][2] = cA[(rb+g  )*36 + ks*8 + tg + 4];
                af[mt][3] = cA[(rb+g+8)*36 + ks*8 + tg + 4];
            }
            #pragma unroll
            for (int nt = 0; nt < 4; nt++) {
                int rb = wn*32 + nt*8 + g;
                bf[nt][0] = cW[rb*36 + ks*8 + tg];
                bf[nt][1] = cW[rb*36 + ks*8 + tg + 4];
            }
            #pragma unroll
            for (int mt = 0; mt < 4; mt++)
                #pragma unroll
                for (int nt = 0; nt < 4; nt++)
                    mma8(acc[mt][nt], af[mt], bf[nt][0], bf[nt][1]);
        }
    }
    #pragma unroll
    for (int mt = 0; mt < 4; mt++) {
        int r = m0 + wm*64 + mt*16 + g;
        #pragma unroll
        for (int nt = 0; nt < 4; nt++) {
            float v0 = acc[mt][nt][0], v1 = acc[mt][nt][1];
            float v2 = acc[mt][nt][2], v3 = acc[mt][nt][3];
            if (mode == 2) {
                uint32_t lo = f2bf2(v0, v1);
                uint32_t hi = f2bf2(v2, v3);
                int c0  = o0 + wn*32 + nt*8 + 2*tg;
                int blk = c0 >> 6;
                int d   = c0 & 63;
                int slot = (nt & 1) ? (2*tg + 1) : (2*tg);
                uint32_t* kp = g_PksU + (size_t)r*256 + blk*32 + (d >> 4)*8 + slot;
                kp[0]     = lo;
                kp[8*256] = hi;
            } else {
                float* cp = C + (size_t)r*O + o0 + wn*32 + nt*8;
                *(float2*)(cp + 2*tg)       = make_float2(v0, v1);
                *(float2*)(cp + 8*O + 2*tg) = make_float2(v2, v3);
            }
        }
    }
}

__global__ __launch_bounds__(256, 2) void gemm_proj_tc()
{
    extern __shared__ float gdsm[];
    int job = blockIdx.x >> 2;
    int ot  = blockIdx.x & 3;
    int m0  = blockIdx.y << 7;
    const float* A; const float* W; float* C; int mode;
    switch (job) {
        case 0: A = g_tsh; W = g_tWqs; C = g_Pqs; mode = 0; break;
        case 1: A = g_tsh; W = g_tWkc; C = g_Pkc; mode = 0; break;
        case 2: A = g_tsh; W = g_tWvc; C = g_Pvc; mode = 0; break;
        case 3: A = g_tsh; W = g_tWks; C = (float*)g_PksU; mode = 2; break;
        default: A = g_ts; W = g_tWqc; C = g_Pqc; mode = 0; break;
    }
    gemm_tc_tile<512,512>(A, W, C, m0, ot << 7, mode, gdsm);
}

__global__ __launch_bounds__(256, 2) void gemm_vs_tc()
{
    extern __shared__ float gdsm[];
    gemm_tc_tile<128,128>(g_th, g_tWvs, g_Pvs, blockIdx.x << 7, 0, 0, gdsm);
}

// ============ repack V_s (sliced) + column-sum reduce ============
__global__ __launch_bounds__(256) void repack_v()
{
    __shared__ float4 red[256];
    int slice = blockIdx.x;   // 0..7
    int bh    = blockIdx.y;   // 0..15
    int b = bh >> 3, h = bh & 7;
    const float* Vb = g_Pvs + ((size_t)b*NTOK + h*512)*128;
    uint32_t* Vp = g_Vp + (size_t)bh*32768;
    int tid = threadIdx.x;
    float4 part = make_float4(0.f, 0.f, 0.f, 0.f);
    #pragma unroll
    for (int it = 0; it < 4; it++) {
        int i = slice*1024 + it*256 + tid;
        int key2 = i >> 2, cg = (i & 3) << 2;
        float4 v0 = *(const float4*)(Vb + (size_t)(2*key2)*16 + cg);
        float4 v1 = *(const float4*)(Vb + (size_t)(2*key2+1)*16 + cg);
        uint4 pk;
        pk.x = f2bf2(v0.x, v1.x);
        pk.y = f2bf2(v0.y, v1.y);
        pk.z = f2bf2(v0.z, v1.z);
        pk.w = f2bf2(v0.w, v1.w);
        *(uint4*)(Vp + (size_t)key2*16 + cg) = pk;
        part.x += v0.x + v1.x;
        part.y += v0.y + v1.y;
        part.z += v0.z + v1.z;
        part.w += v0.w + v1.w;
    }
    red[tid] = part;
    __syncthreads();
    if (tid < 4) {
        float4 ssum = make_float4(0.f, 0.f, 0.f, 0.f);
        for (int t = tid; t < 256; t += 4) {
            float4 v = red[t];
            ssum.x += v.x; ssum.y += v.y; ssum.z += v.z; ssum.w += v.w;
        }
        *(float4*)(g_VcsP + (bh*8 + slice)*16 + tid*4) = ssum;
    }
}

__global__ void vcs_reduce()
{
    int tid = threadIdx.x;      // 256 threads: bh = tid>>4, col = tid&15
    int bh = tid >> 4, col = tid & 15;
    float s = 0.f;
    #pragma unroll
    for (int p = 0; p < 8; p++)
        s += g_VcsP[(bh*8 + p)*16 + col];
    g_Vcs[bh*16 + col] = s;
}

// =================== channel attention (fp32, unchanged) ===================
__global__ __launch_bounds__(256) void ca_scores()
{
    __shared__ float Qs[32][68];
    __shared__ float Ks[32][68];
    int slice = blockIdx.x;
    int bh    = blockIdx.y;
    int b = bh >> 3, h = bh & 7;
    const float* Qc = g_Pqc + ((size_t)b*NTOK + h*512) * 512;
    const float* Kc = g_Pkc + ((size_t)b*NTOK + h*512) * 512;
    int tid = threadIdx.x;
    int lr = tid >> 3, lc = (tid & 7) << 3;
    int i0 = (tid >> 4) << 2, j0 = (tid & 15) << 2;
    float acc[4][4];
    #pragma unroll
    for (int i = 0; i < 4; i++)
        #pragma unroll
        for (int j = 0; j < 4; j++) acc[i][j] = 0.f;
    #pragma unroll 1
    for (int nt = 0; nt < 8; nt++) {
        int nb = slice*256 + (nt << 5);
        const float* qp = Qc + (size_t)(nb + lr)*64 + lc;
        const float* kp = Kc + (size_t)(nb + lr)*64 + lc;
        float4 q0 = *(const float4*)qp, q1 = *(const float4*)(qp+4);
        float4 k0 = *(const float4*)kp, k1 = *(const float4*)(kp+4);
        __syncthreads();
        *(float4*)&Qs[lr][lc] = q0; *(float4*)&Qs[lr][lc+4] = q1;
        *(float4*)&Ks[lr][lc] = k0; *(float4*)&Ks[lr][lc+4] = k1;
        __syncthreads();
        #pragma unroll 8
        for (int nn = 0; nn < 32; nn++) {
            float4 q = *(const float4*)&Qs[nn][i0];
            float4 k = *(const float4*)&Ks[nn][j0];
            float qa[4] = {q.x,q.y,q.z,q.w};
            float ka[4] = {k.x,k.y,k.z,k.w};
            #pragma unroll
            for (int i = 0; i < 4; i++)
                #pragma unroll
                for (int j = 0; j < 4; j++)
                    acc[i][j] = fmaf(qa[i], ka[j], acc[i][j]);
        }
    }
    float* dst = g_Sca + ((size_t)(bh*16 + slice)*64)*64;
    #pragma unroll
    for (int i = 0; i < 4; i++)
        *(float4*)&dst[(i0+i)*64 + j0] = make_float4(acc[i][0],acc[i][1],acc[i][2],acc[i][3]);
}

__global__ void ca_reduce(const float* __restrict__ temp)
{
    int bh = blockIdx.x;
    int h  = bh & 7;
    int i  = threadIdx.x;
    float scale = 0.125f * temp[h];
    float row[64];
    #pragma unroll
    for (int j = 0; j < 64; j++) {
        float s = 0.f;
        #pragma unroll
        for (int p = 0; p < 16; p++)
            s += g_Sca[((size_t)(bh*16+p)*64 + i)*64 + j];
        row[j] = s * scale;
    }
    float m = row[0];
    #pragma unroll
    for (int j = 1; j < 64; j++) m = fmaxf(m, row[j]);
    float sum = 0.f;
    #pragma unroll
    for (int j = 0; j < 64; j++) { row[j] = __expf(row[j]-m); sum += row[j]; }
    float inv = 1.f / sum;
    #pragma unroll
    for (int j = 0; j < 64; j++)
        g_Pca[((size_t)bh*64 + i)*64 + j] = row[j]*inv;
}

__global__ __launch_bounds__(256) void ca_out(float* __restrict__ out)
{
    __shared__ float Pts[64][68];
    __shared__ float Vt[64][68];
    int mt = blockIdx.x;
    int bh = blockIdx.y;
    int b = bh >> 3, h = bh & 7;
    int tid = threadIdx.x;
    {
        int i  = tid & 63;
        int jc = (tid >> 6) << 4;
        const float* pp = g_Pca + ((size_t)bh*64 + i)*64 + jc;
        #pragma unroll
        for (int t = 0; t < 4; t++) {
            float4 v = *(const float4*)(pp + t*4);
            Pts[jc+t*4+0][i] = v.x; Pts[jc+t*4+1][i] = v.y;
            Pts[jc+t*4+2][i] = v.z; Pts[jc+t*4+3][i] = v.w;
        }
    }
    {
        int mm = tid & 63;
        int jc = (tid >> 6) << 4;
        const float* vp = g_Pvc + ((size_t)b*NTOK + h*512)*512 + (size_t)(mt*64 + mm)*64 + jc;
        #pragma unroll
        for (int t = 0; t < 4; t++) {
            float4 v = *(const float4*)(vp + t*4);
            Vt[jc+t*4+0][mm] = v.x; Vt[jc+t*4+1][mm] = v.y;
            Vt[jc+t*4+2][mm] = v.z; Vt[jc+t*4+3][mm] = v.w;
        }
    }
    __syncthreads();
    int i0 = (tid >> 4) << 2, m0 = (tid & 15) << 2;
    float acc[4][4];
    #pragma unroll
    for (int i = 0; i < 4; i++)
        #pragma unroll
        for (int j = 0; j < 4; j++) acc[i][j] = 0.f;
    #pragma unroll 8
    for (int j = 0; j < 64; j++) {
        float4 p = *(const float4*)&Pts[j][i0];
        float4 v = *(const float4*)&Vt[j][m0];
        float pa[4] = {p.x,p.y,p.z,p.w};
        float va[4] = {v.x,v.y,v.z,v.w};
        #pragma unroll
        for (int i = 0; i < 4; i++)
            #pragma unroll
            for (int m = 0; m < 4; m++)
                acc[i][m] = fmaf(pa[i], va[m], acc[i][m]);
    }
    int rowoff  = mt >> 3;
    int colbase = (mt & 7)*64 + m0;
    #pragma unroll
    for (int i = 0; i < 4; i++) {
        int row = h*512 + (i0+i)*8 + rowoff;
        float* op = out + ((size_t)b*NTOK + row)*640 + colbase;
        *(float4*)op = make_float4(acc[i][0],acc[i][1],acc[i][2],acc[i][3]);
    }
}

// ====== spatial flash: all-bf16 mma, 1+u softmax decomposition (R11) ======
#define KSTRU 40
#define FKOFFU(s) ((s)*2560)
#define FVOFFU(s) (7680 + (s)*768)
#define FSMEM (9984 * 4)

__global__ __launch_bounds__(256, 2) void flash_mma(const float* __restrict__ t2,
                                                    float* __restrict__ out)
{
    extern __shared__ float sm[];
    uint32_t* smu = (uint32_t*)sm;
    int tid = threadIdx.x, w = tid >> 5, lane = tid & 31;
    int g = lane >> 2, tg = lane & 3;
    int qt = blockIdx.x, bh = blockIdx.y;
    int b = bh >> 3, h = bh & 7;
    const float*    Qb  = g_Pqs  + ((size_t)b*NTOK + h*512)*512;
    const uint32_t* KbU = g_PksU + ((size_t)b*NTOK + h*512)*256;
    const uint32_t* Vpg = g_Vp + (size_t)bh*32768;
    float qscale = 0.125f * t2[h] * 1.4426950408889634f;

    int kr = tid >> 2, kq = tid & 3;
    uint32_t kdst[3], vdst[3];
    #pragma unroll
    for (int st = 0; st < 3; st++) {
        kdst[st] = smem_u32(smu + FKOFFU(st) + kr*KSTRU + kq*8);
        vdst[st] = smem_u32(smu + FVOFFU(st) + kr*24 + kq*4);
    }
    const uint32_t* ksrc = KbU + (size_t)kr*32 + kq*8;
    const uint32_t* vsrc = Vpg + (size_t)kr*16 + kq*4;

    int q0 = w << 4;
    uint32_t qa[4][4];
    {
        const float* qr0 = Qb + (size_t)(qt*128 + q0 + g)*64;
        const float* qr1 = qr0 + 8*64;
        #pragma unroll
        for (int kd = 0; kd < 4; kd++) {
            int d0 = kd*16 + 2*tg;
            qa[kd][0] = f2bf2(qr0[d0]*qscale,   qr0[d0+1]*qscale);
            qa[kd][1] = f2bf2(qr1[d0]*qscale,   qr1[d0+1]*qscale);
            qa[kd][2] = f2bf2(qr0[d0+8]*qscale, qr0[d0+9]*qscale);
            qa[kd][3] = f2bf2(qr1[d0+8]*qscale, qr1[d0+9]*qscale);
        }
    }

    float Ofr[2][4];
    #pragma unroll
    for (int n = 0; n < 2; n++)
        #pragma unroll
        for (int e = 0; e < 4; e++) Ofr[n][e] = 0.f;
    float l0 = 0.f, l1 = 0.f;

    cpasync16(kdst[0], ksrc); cpasync16(kdst[0] + 16, ksrc + 4);
    if (tid < 128) cpasync16(vdst[0], vsrc);
    CP_COMMIT();
    cpasync16(kdst[1], ksrc + 2048); cpasync16(kdst[1] + 16, ksrc + 2052);
    if (tid < 128) cpasync16(vdst[1], vsrc + 512);
    CP_COMMIT();

    #pragma unroll 1
    for (int c = 0; c < 64; c++) {
        if (c + 1 < 64) { CP_WAIT1(); } else { CP_WAIT0(); }
        __syncthreads();
        if (c + 2 < 64) {
            int st = (c + 2) % 3;
            const uint32_t* kp = ksrc + (size_t)(c+2)*2048;
            const uint32_t* vp = vsrc + (size_t)(c+2)*512;
            cpasync16(kdst[st], kp); cpasync16(kdst[st] + 16, kp + 4);
            if (tid < 128) cpasync16(vdst[st], vp);
            CP_COMMIT();
        }
        int st = c % 3;
        const uint32_t* Kc = smu + FKOFFU(st);
        const uint32_t* Vc = smu + FVOFFU(st);

        #pragma unroll
        for (int ks = 0; ks < 4; ks++) {
            float s0[4] = {0.f,0.f,0.f,0.f};
            float s1[4] = {0.f,0.f,0.f,0.f};
            const uint32_t* kr0 = Kc + (ks*16 + g)*KSTRU;
            const uint32_t* kr1 = kr0 + 8*KSTRU;
            #pragma unroll
            for (int kd = 0; kd < 4; kd++) {
                uint2 k0 = *(const uint2*)(kr0 + kd*8 + 2*tg);
                uint2 k1 = *(const uint2*)(kr1 + kd*8 + 2*tg);
                mma16bf(s0, qa[kd], k0.x, k0.y);
                mma16bf(s1, qa[kd], k1.x, k1.y);
            }
            float u00 = ex2f(s0[0]) - 1.f, u01 = ex2f(s0[1]) - 1.f;
            float u02 = ex2f(s0[2]) - 1.f, u03 = ex2f(s0[3]) - 1.f;
            float u10 = ex2f(s1[0]) - 1.f, u11 = ex2f(s1[1]) - 1.f;
            float u12 = ex2f(s1[2]) - 1.f, u13 = ex2f(s1[3]) - 1.f;
            l0 += (u00 + u01) + (u10 + u11);
            l1 += (u02 + u03) + (u12 + u13);
            uint32_t ap[4];
            ap[0] = f2bf2(u00, u01);
            ap[1] = f2bf2(u02, u03);
            ap[2] = f2bf2(u10, u11);
            ap[3] = f2bf2(u12, u13);
            const uint32_t* vr0 = Vc + (ks*8 + tg)*24;
            const uint32_t* vr1 = Vc + (ks*8 + tg + 4)*24;
            mma16bf(Ofr[0], ap, vr0[g],     vr1[g]);
            mma16bf(Ofr[1], ap, vr0[g + 8], vr1[g + 8]);
        }
    }
    l0 += __shfl_xor_sync(0xffffffffu, l0, 1);
    l0 += __shfl_xor_sync(0xffffffffu, l0, 2);
    l1 += __shfl_xor_sync(0xffffffffu, l1, 1);
    l1 += __shfl_xor_sync(0xffffffffu, l1, 2);

    float inv0 = 1.f / (4096.f + l0), inv1 = 1.f / (4096.f + l1);
    int n_g  = qt*128 + q0 + g;
    int n_g8 = n_g + 8;
    float* op0 = out + ((size_t)b*NTOK + h*512 + (n_g  >> 3))*640 + 512 + (n_g  & 7)*16;
    float* op1 = out + ((size_t)b*NTOK + h*512 + (n_g8 >> 3))*640 + 512 + (n_g8 & 7)*16;
    #pragma unroll
    for (int nt = 0; nt < 2; nt++) {
        int cbase = nt*8 + 2*tg;
        float2 cs = *(const float2*)(g_Vcs + bh*16 + cbase);
        float2 a, c2;
        a.x  = (cs.x + Ofr[nt][0])*inv0; a.y  = (cs.y + Ofr[nt][1])*inv0;
        c2.x = (cs.x + Ofr[nt][2])*inv1; c2.y = (cs.y + Ofr[nt][3])*inv1;
        *(float2*)(op0 + cbase) = a;
        *(float2*)(op1 + cbase) = c2;
    }
}

// =================== launch (sequential, R11 order) ===================
extern "C" void kernel_launch(void* const* d_in, const int* in_sizes, int n_in,
                              void* d_out, int out_size)
{
    const float* s_in = (const float*)d_in[0];
    const float* h_in = (const float*)d_in[1];
    const float* sh   = (const float*)d_in[2];
    const float* t1   = (const float*)d_in[3];
    const float* t2   = (const float*)d_in[4];
    const float* Wqc  = (const float*)d_in[5];
    const float* Wqs  = (const float*)d_in[6];
    const float* Wkc  = (const float*)d_in[7];
    const float* Wvc  = (const float*)d_in[8];
    const float* Wks  = (const float*)d_in[9];
    const float* Wvs  = (const float*)d_in[10];
    float* out = (float*)d_out;

    cudaFuncSetAttribute(flash_mma, cudaFuncAttributeMaxDynamicSharedMemorySize, FSMEM);
    cudaFuncSetAttribute(gemm_proj_tc, cudaFuncAttributeMaxDynamicSharedMemorySize, GSMEM);
    cudaFuncSetAttribute(gemm_vs_tc, cudaFuncAttributeMaxDynamicSharedMemorySize, GSMEM);

    prep<<<(SEGT + 255) / 256, 256>>>(
        (const float4*)s_in, (const float4*)sh, (const float4*)h_in,
        (const float4*)Wqc, (const float4*)Wqs, (const float4*)Wkc,
        (const float4*)Wvc, (const float4*)Wks, (const float4*)Wvs);
    gemm_proj_tc<<<dim3(20,64), 256, GSMEM>>>();
    gemm_vs_tc<<<64, 256, GSMEM>>>();
    repack_v<<<dim3(8,16), 256>>>();
    vcs_reduce<<<1, 256>>>();
    flash_mma<<<dim3(32,16), 256, FSMEM>>>(t2, out);
    ca_scores<<<dim3(16,16), 256>>>();
    ca_reduce<<<16, 64>>>(t1);
    ca_out<<<dim3(64,16), 256>>>(out);
}

// round 15
// speedup vs baseline: 1.0726x; 1.0395x over previous
#include <cuda_runtime.h>
#include <math.h>
#include <stdint.h>

#define NB 2
#define NTOK 4096

__device__ float g_Pqc[8192*512];
__device__ float g_Pqs[8192*512];
__device__ float g_Pkc[8192*512];
__device__ float g_Pvc[8192*512];
__device__ uint32_t g_PksU[8192*256];   // K_s as bf16x2 pairs, slot-permuted
__device__ float g_Pvs[8192*128];       // V_s fp32 (unrounded)
__device__ uint32_t g_Vp[16*2048*16];   // V_s as bf16x2 key-pairs
__device__ float g_Vcs[16*16];          // V_s column sums per (b,h)
__device__ float g_VcsP[128*16];        // partial column sums
__device__ float g_Sca[16*16*64*64];
__device__ float g_Pca[16*64*64];
__device__ float g_ts [8192*512];
__device__ float g_tsh[8192*512];
__device__ float g_th [8192*128];
__device__ float g_tWqc[512*512];
__device__ float g_tWqs[512*512];
__device__ float g_tWkc[512*512];
__device__ float g_tWvc[512*512];
__device__ float g_tWks[512*512];
__device__ float g_tWvs[128*128];

// =================== helpers ===================
__device__ __forceinline__ uint32_t f2tf(float x) {
    uint32_t r; asm("cvt.rna.tf32.f32 %0, %1;" : "=r"(r) : "f"(x)); return r;
}
__device__ __forceinline__ uint32_t f2bf2(float lo, float hi) {
    uint32_t r; asm("cvt.rn.bf16x2.f32 %0, %1, %2;" : "=r"(r) : "f"(hi), "f"(lo)); return r;
}
__device__ __forceinline__ float ex2f(float x) {
    float r; asm("ex2.approx.ftz.f32 %0, %1;" : "=f"(r) : "f"(x)); return r;
}
__device__ __forceinline__ void mma8(float* d, const uint32_t* a, uint32_t b0, uint32_t b1) {
    asm volatile(
        "mma.sync.aligned.m16n8k8.row.col.f32.tf32.tf32.f32 "
        "{%0,%1,%2,%3},{%4,%5,%6,%7},{%8,%9},{%0,%1,%2,%3};"
        : "+f"(d[0]), "+f"(d[1]), "+f"(d[2]), "+f"(d[3])
        : "r"(a[0]), "r"(a[1]), "r"(a[2]), "r"(a[3]), "r"(b0), "r"(b1));
}
__device__ __forceinline__ void mma16bf(float* d, const uint32_t* a, uint32_t b0, uint32_t b1) {
    asm volatile(
        "mma.sync.aligned.m16n8k16.row.col.f32.bf16.bf16.f32 "
        "{%0,%1,%2,%3},{%4,%5,%6,%7},{%8,%9},{%0,%1,%2,%3};"
        : "+f"(d[0]), "+f"(d[1]), "+f"(d[2]), "+f"(d[3])
        : "r"(a[0]), "r"(a[1]), "r"(a[2]), "r"(a[3]), "r"(b0), "r"(b1));
}
__device__ __forceinline__ uint32_t smem_u32(const void* p) {
    uint32_t a;
    asm("{ .reg .u64 t; cvta.to.shared.u64 t, %1; cvt.u32.u64 %0, t; }" : "=r"(a) : "l"(p));
    return a;
}
__device__ __forceinline__ void cpasync16(uint32_t dst, const void* src) {
    asm volatile("cp.async.ca.shared.global [%0], [%1], 16;" :: "r"(dst), "l"(src));
}
#define CP_COMMIT() asm volatile("cp.async.commit_group;" ::: "memory")
#define CP_WAIT1()  asm volatile("cp.async.wait_group 1;" ::: "memory")
#define CP_WAIT0()  asm volatile("cp.async.wait_group 0;" ::: "memory")

// =================== prep: round all inputs to tf32 once (R11) ===================
#define SEG0 1048576
#define SEG1 2097152
#define SEG2 2359296
#define SEG3 2424832
#define SEG4 2490368
#define SEG5 2555904
#define SEG6 2621440
#define SEG7 2686976
#define SEGT 2691072
__global__ __launch_bounds__(256) void prep(
    const float4* __restrict__ s, const float4* __restrict__ sh, const float4* __restrict__ h,
    const float4* __restrict__ wqc, const float4* __restrict__ wqs, const float4* __restrict__ wkc,
    const float4* __restrict__ wvc, const float4* __restrict__ wks, const float4* __restrict__ wvs)
{
    int i = blockIdx.x * blockDim.x + threadIdx.x;
    if (i >= SEGT) return;
    const float4* src; float4* dst; int off;
    if      (i < SEG0) { src = s;   dst = (float4*)g_ts;   off = i; }
    else if (i < SEG1) { src = sh;  dst = (float4*)g_tsh;  off = i - SEG0; }
    else if (i < SEG2) { src = h;   dst = (float4*)g_th;   off = i - SEG1; }
    else if (i < SEG3) { src = wqc; dst = (float4*)g_tWqc; off = i - SEG2; }
    else if (i < SEG4) { src = wqs; dst = (float4*)g_tWqs; off = i - SEG3; }
    else if (i < SEG5) { src = wkc; dst = (float4*)g_tWkc; off = i - SEG4; }
    else if (i < SEG6) { src = wvc; dst = (float4*)g_tWvc; off = i - SEG5; }
    else if (i < SEG7) { src = wks; dst = (float4*)g_tWks; off = i - SEG6; }
    else               { src = wvs; dst = (float4*)g_tWvs; off = i - SEG7; }
    float4 v = src[off];
    dst[off] = make_float4(__uint_as_float(f2tf(v.x)), __uint_as_float(f2tf(v.y)),
                           __uint_as_float(f2tf(v.z)), __uint_as_float(f2tf(v.w)));
}

// =================== tf32 TC GEMM, 3-stage cp.async (R11, proven) ===================
#define GSTG 2560
#define GSMEM (3*GSTG*2*4)

// mode: 0 = plain fp32 out, 2 = bf16x2 pair-permuted out (K_s)
template<int K, int O>
__device__ __forceinline__ void gemm_tc_tile(const float* __restrict__ A,
                                             const float* __restrict__ W,
                                             float* __restrict__ C,
                                             int m0, int o0, int mode,
                                             float* dynsm)
{
    const int NC = K / 16;
    float* sA = dynsm;
    float* sW = dynsm + 3*GSTG;
    int tid = threadIdx.x, w = tid >> 5, lane = tid & 31;
    int g = lane >> 2, tg = lane & 3;
    int wm = w >> 2, wn = w & 3;
    int pr = tid >> 1, pc = (tid & 1) << 3;
    const float* Ap = A + (size_t)(m0 + pr) * K + pc;
    const float* Wp = W + (size_t)(o0 + pr) * K + pc;
    uint32_t sAb[3], sWb[3];
    #pragma unroll
    for (int st = 0; st < 3; st++) {
        sAb[st] = smem_u32(sA + st*GSTG + pr*20 + pc);
        sWb[st] = smem_u32(sW + st*GSTG + pr*20 + pc);
    }

    float acc[4][4][4];
    #pragma unroll
    for (int mt = 0; mt < 4; mt++)
        #pragma unroll
        for (int nt = 0; nt < 4; nt++)
            #pragma unroll
            for (int e = 0; e < 4; e++) acc[mt][nt][e] = 0.f;

    cpasync16(sAb[0],      Ap);      cpasync16(sAb[0] + 16, Ap + 4);
    cpasync16(sWb[0],      Wp);      cpasync16(sWb[0] + 16, Wp + 4);
    CP_COMMIT();
    cpasync16(sAb[1],      Ap + 16); cpasync16(sAb[1] + 16, Ap + 20);
    cpasync16(sWb[1],      Wp + 16); cpasync16(sWb[1] + 16, Wp + 20);
    CP_COMMIT();

    #pragma unroll 1
    for (int c = 0; c < NC; c++) {
        if (c + 1 < NC) { CP_WAIT1(); } else { CP_WAIT0(); }
        __syncthreads();
        if (c + 2 < NC) {
            int st = (c + 2) % 3;
            const float* ap = Ap + (c+2)*16;
            const float* wp = Wp + (c+2)*16;
            cpasync16(sAb[st],      ap); cpasync16(sAb[st] + 16, ap + 4);
            cpasync16(sWb[st],      wp); cpasync16(sWb[st] + 16, wp + 4);
            CP_COMMIT();
        }
        int st = c % 3;
        const uint32_t* cA = (const uint32_t*)(sA + st*GSTG);
        const uint32_t* cW = (const uint32_t*)(sW + st*GSTG);
        #pragma unroll
        for (int ks = 0; ks < 2; ks++) {
            uint32_t af[4][4], bf[4][2];
            #pragma unroll
            for (int mt = 0; mt < 4; mt++) {
                int rb = wm*64 + mt*16;
                af[mt][0] = cA[(rb+g  )*20 + ks*8 + tg];
                af[mt][1] = cA[(rb+g+8)*20 + ks*8 + tg];
                af[mt][2] = cA[(rb+g  )*20 + ks*8 + tg + 4];
                af[mt][3] = cA[(rb+g+8)*20 + ks*8 + tg + 4];
            }
            #pragma unroll
            for (int nt = 0; nt < 4; nt++) {
                int rb = wn*32 + nt*8 + g;
                bf[nt][0] = cW[rb*20 + ks*8 + tg];
                bf[nt][1] = cW[rb*20 + ks*8 + tg + 4];
            }
            #pragma unroll
            for (int mt = 0; mt < 4; mt++)
                #pragma unroll
                for (int nt = 0; nt < 4; nt++)
                    mma8(acc[mt][nt], af[mt], bf[nt][0], bf[nt][1]);
        }
    }
    #pragma unroll
    for (int mt = 0; mt < 4; mt++) {
        int r = m0 + wm*64 + mt*16 + g;
        #pragma unroll
        for (int nt = 0; nt < 4; nt++) {
            float v0 = acc[mt][nt][0], v1 = acc[mt][nt][1];
            float v2 = acc[mt][nt][2], v3 = acc[mt][nt][3];
            if (mode == 2) {
                uint32_t lo = f2bf2(v0, v1);
                uint32_t hi = f2bf2(v2, v3);
                int c0  = o0 + wn*32 + nt*8 + 2*tg;
                int blk = c0 >> 6;
                int d   = c0 & 63;
                int slot = (nt & 1) ? (2*tg + 1) : (2*tg);
                uint32_t* kp = g_PksU + (size_t)r*256 + blk*32 + (d >> 4)*8 + slot;
                kp[0]     = lo;
                kp[8*256] = hi;
            } else {
                float* cp = C + (size_t)r*O + o0 + wn*32 + nt*8;
                *(float2*)(cp + 2*tg)       = make_float2(v0, v1);
                *(float2*)(cp + 8*O + 2*tg) = make_float2(v2, v3);
            }
        }
    }
}

__global__ __launch_bounds__(256, 2) void gemm_proj_tc()
{
    extern __shared__ float gdsm[];
    int job = blockIdx.x >> 2;
    int ot  = blockIdx.x & 3;
    int m0  = blockIdx.y << 7;
    const float* A; const float* W; float* C; int mode;
    switch (job) {
        case 0: A = g_tsh; W = g_tWqs; C = g_Pqs; mode = 0; break;
        case 1: A = g_tsh; W = g_tWkc; C = g_Pkc; mode = 0; break;
        case 2: A = g_tsh; W = g_tWvc; C = g_Pvc; mode = 0; break;
        case 3: A = g_tsh; W = g_tWks; C = (float*)g_PksU; mode = 2; break;
        default: A = g_ts; W = g_tWqc; C = g_Pqc; mode = 0; break;
    }
    gemm_tc_tile<512,512>(A, W, C, m0, ot << 7, mode, gdsm);
}

__global__ __launch_bounds__(256, 2) void gemm_vs_tc()
{
    extern __shared__ float gdsm[];
    gemm_tc_tile<128,128>(g_th, g_tWvs, g_Pvs, blockIdx.x << 7, 0, 0, gdsm);
}

// ============ repack V_s (sliced, R14) + column-sum reduce ============
__global__ __launch_bounds__(256) void repack_v()
{
    __shared__ float4 red[256];
    int slice = blockIdx.x;   // 0..7
    int bh    = blockIdx.y;   // 0..15
    int b = bh >> 3, h = bh & 7;
    const float* Vb = g_Pvs + ((size_t)b*NTOK + h*512)*128;
    uint32_t* Vp = g_Vp + (size_t)bh*32768;
    int tid = threadIdx.x;
    float4 part = make_float4(0.f, 0.f, 0.f, 0.f);
    #pragma unroll
    for (int it = 0; it < 4; it++) {
        int i = slice*1024 + it*256 + tid;
        int key2 = i >> 2, cg = (i & 3) << 2;
        float4 v0 = *(const float4*)(Vb + (size_t)(2*key2)*16 + cg);
        float4 v1 = *(const float4*)(Vb + (size_t)(2*key2+1)*16 + cg);
        uint4 pk;
        pk.x = f2bf2(v0.x, v1.x);
        pk.y = f2bf2(v0.y, v1.y);
        pk.z = f2bf2(v0.z, v1.z);
        pk.w = f2bf2(v0.w, v1.w);
        *(uint4*)(Vp + (size_t)key2*16 + cg) = pk;
        part.x += v0.x + v1.x;
        part.y += v0.y + v1.y;
        part.z += v0.z + v1.z;
        part.w += v0.w + v1.w;
    }
    red[tid] = part;
    __syncthreads();
    if (tid < 4) {
        float4 ssum = make_float4(0.f, 0.f, 0.f, 0.f);
        for (int t = tid; t < 256; t += 4) {
            float4 v = red[t];
            ssum.x += v.x; ssum.y += v.y; ssum.z += v.z; ssum.w += v.w;
        }
        *(float4*)(g_VcsP + (bh*8 + slice)*16 + tid*4) = ssum;
    }
}

__global__ void vcs_reduce()
{
    int tid = threadIdx.x;      // 256 threads: bh = tid>>4, col = tid&15
    int bh = tid >> 4, col = tid & 15;
    float s = 0.f;
    #pragma unroll
    for (int p = 0; p < 8; p++)
        s += g_VcsP[(bh*8 + p)*16 + col];
    g_Vcs[bh*16 + col] = s;
}

// =================== channel attention (fp32, unchanged) ===================
__global__ __launch_bounds__(256) void ca_scores()
{
    __shared__ float Qs[32][68];
    __shared__ float Ks[32][68];
    int slice = blockIdx.x;
    int bh    = blockIdx.y;
    int b = bh >> 3, h = bh & 7;
    const float* Qc = g_Pqc + ((size_t)b*NTOK + h*512) * 512;
    const float* Kc = g_Pkc + ((size_t)b*NTOK + h*512) * 512;
    int tid = threadIdx.x;
    int lr = tid >> 3, lc = (tid & 7) << 3;
    int i0 = (tid >> 4) << 2, j0 = (tid & 15) << 2;
    float acc[4][4];
    #pragma unroll
    for (int i = 0; i < 4; i++)
        #pragma unroll
        for (int j = 0; j < 4; j++) acc[i][j] = 0.f;
    #pragma unroll 1
    for (int nt = 0; nt < 8; nt++) {
        int nb = slice*256 + (nt << 5);
        const float* qp = Qc + (size_t)(nb + lr)*64 + lc;
        const float* kp = Kc + (size_t)(nb + lr)*64 + lc;
        float4 q0 = *(const float4*)qp, q1 = *(const float4*)(qp+4);
        float4 k0 = *(const float4*)kp, k1 = *(const float4*)(kp+4);
        __syncthreads();
        *(float4*)&Qs[lr][lc] = q0; *(float4*)&Qs[lr][lc+4] = q1;
        *(float4*)&Ks[lr][lc] = k0; *(float4*)&Ks[lr][lc+4] = k1;
        __syncthreads();
        #pragma unroll 8
        for (int nn = 0; nn < 32; nn++) {
            float4 q = *(const float4*)&Qs[nn][i0];
            float4 k = *(const float4*)&Ks[nn][j0];
            float qa[4] = {q.x,q.y,q.z,q.w};
            float ka[4] = {k.x,k.y,k.z,k.w};
            #pragma unroll
            for (int i = 0; i < 4; i++)
                #pragma unroll
                for (int j = 0; j < 4; j++)
                    acc[i][j] = fmaf(qa[i], ka[j], acc[i][j]);
        }
    }
    float* dst = g_Sca + ((size_t)(bh*16 + slice)*64)*64;
    #pragma unroll
    for (int i = 0; i < 4; i++)
        *(float4*)&dst[(i0+i)*64 + j0] = make_float4(acc[i][0],acc[i][1],acc[i][2],acc[i][3]);
}

__global__ void ca_reduce(const float* __restrict__ temp)
{
    int bh = blockIdx.x;
    int h  = bh & 7;
    int i  = threadIdx.x;
    float scale = 0.125f * temp[h];
    float row[64];
    #pragma unroll
    for (int j = 0; j < 64; j++) {
        float s = 0.f;
        #pragma unroll
        for (int p = 0; p < 16; p++)
            s += g_Sca[((size_t)(bh*16+p)*64 + i)*64 + j];
        row[j] = s * scale;
    }
    float m = row[0];
    #pragma unroll
    for (int j = 1; j < 64; j++) m = fmaxf(m, row[j]);
    float sum = 0.f;
    #pragma unroll
    for (int j = 0; j < 64; j++) { row[j] = __expf(row[j]-m); sum += row[j]; }
    float inv = 1.f / sum;
    #pragma unroll
    for (int j = 0; j < 64; j++)
        g_Pca[((size_t)bh*64 + i)*64 + j] = row[j]*inv;
}

__global__ __launch_bounds__(256) void ca_out(float* __restrict__ out)
{
    __shared__ float Pts[64][68];
    __shared__ float Vt[64][68];
    int mt = blockIdx.x;
    int bh = blockIdx.y;
    int b = bh >> 3, h = bh & 7;
    int tid = threadIdx.x;
    {
        int i  = tid & 63;
        int jc = (tid >> 6) << 4;
        const float* pp = g_Pca + ((size_t)bh*64 + i)*64 + jc;
        #pragma unroll
        for (int t = 0; t < 4; t++) {
            float4 v = *(const float4*)(pp + t*4);
            Pts[jc+t*4+0][i] = v.x; Pts[jc+t*4+1][i] = v.y;
            Pts[jc+t*4+2][i] = v.z; Pts[jc+t*4+3][i] = v.w;
        }
    }
    {
        int mm = tid & 63;
        int jc = (tid >> 6) << 4;
        const float* vp = g_Pvc + ((size_t)b*NTOK + h*512)*512 + (size_t)(mt*64 + mm)*64 + jc;
        #pragma unroll
        for (int t = 0; t < 4; t++) {
            float4 v = *(const float4*)(vp + t*4);
            Vt[jc+t*4+0][mm] = v.x; Vt[jc+t*4+1][mm] = v.y;
            Vt[jc+t*4+2][mm] = v.z; Vt[jc+t*4+3][mm] = v.w;
        }
    }
    __syncthreads();
    int i0 = (tid >> 4) << 2, m0 = (tid & 15) << 2;
    float acc[4][4];
    #pragma unroll
    for (int i = 0; i < 4; i++)
        #pragma unroll
        for (int j = 0; j < 4; j++) acc[i][j] = 0.f;
    #pragma unroll 8
    for (int j = 0; j < 64; j++) {
        float4 p = *(const float4*)&Pts[j][i0];
        float4 v = *(const float4*)&Vt[j][m0];
        float pa[4] = {p.x,p.y,p.z,p.w};
        float va[4] = {v.x,v.y,v.z,v.w};
        #pragma unroll
        for (int i = 0; i < 4; i++)
            #pragma unroll
            for (int m = 0; m < 4; m++)
                acc[i][m] = fmaf(pa[i], va[m], acc[i][m]);
    }
    int rowoff  = mt >> 3;
    int colbase = (mt & 7)*64 + m0;
    #pragma unroll
    for (int i = 0; i < 4; i++) {
        int row = h*512 + (i0+i)*8 + rowoff;
        float* op = out + ((size_t)b*NTOK + row)*640 + colbase;
        *(float4*)op = make_float4(acc[i][0],acc[i][1],acc[i][2],acc[i][3]);
    }
}

// ====== spatial flash: all-bf16 mma, 1+u softmax decomposition (R11) ======
#define KSTRU 40
#define FKOFFU(s) ((s)*2560)
#define FVOFFU(s) (7680 + (s)*768)
#define FSMEM (9984 * 4)

__global__ __launch_bounds__(256, 2) void flash_mma(const float* __restrict__ t2,
                                                    float* __restrict__ out)
{
    extern __shared__ float sm[];
    uint32_t* smu = (uint32_t*)sm;
    int tid = threadIdx.x, w = tid >> 5, lane = tid & 31;
    int g = lane >> 2, tg = lane & 3;
    int qt = blockIdx.x, bh = blockIdx.y;
    int b = bh >> 3, h = bh & 7;
    const float*    Qb  = g_Pqs  + ((size_t)b*NTOK + h*512)*512;
    const uint32_t* KbU = g_PksU + ((size_t)b*NTOK + h*512)*256;
    const uint32_t* Vpg = g_Vp + (size_t)bh*32768;
    float qscale = 0.125f * t2[h] * 1.4426950408889634f;

    int kr = tid >> 2, kq = tid & 3;
    uint32_t kdst[3], vdst[3];
    #pragma unroll
    for (int st = 0; st < 3; st++) {
        kdst[st] = smem_u32(smu + FKOFFU(st) + kr*KSTRU + kq*8);
        vdst[st] = smem_u32(smu + FVOFFU(st) + kr*24 + kq*4);
    }
    const uint32_t* ksrc = KbU + (size_t)kr*32 + kq*8;
    const uint32_t* vsrc = Vpg + (size_t)kr*16 + kq*4;

    int q0 = w << 4;
    uint32_t qa[4][4];
    {
        const float* qr0 = Qb + (size_t)(qt*128 + q0 + g)*64;
        const float* qr1 = qr0 + 8*64;
        #pragma unroll
        for (int kd = 0; kd < 4; kd++) {
            int d0 = kd*16 + 2*tg;
            qa[kd][0] = f2bf2(qr0[d0]*qscale,   qr0[d0+1]*qscale);
            qa[kd][1] = f2bf2(qr1[d0]*qscale,   qr1[d0+1]*qscale);
            qa[kd][2] = f2bf2(qr0[d0+8]*qscale, qr0[d0+9]*qscale);
            qa[kd][3] = f2bf2(qr1[d0+8]*qscale, qr1[d0+9]*qscale);
        }
    }

    float Ofr[2][4];
    #pragma unroll
    for (int n = 0; n < 2; n++)
        #pragma unroll
        for (int e = 0; e < 4; e++) Ofr[n][e] = 0.f;
    float l0 = 0.f, l1 = 0.f;

    cpasync16(kdst[0], ksrc); cpasync16(kdst[0] + 16, ksrc + 4);
    if (tid < 128) cpasync16(vdst[0], vsrc);
    CP_COMMIT();
    cpasync16(kdst[1], ksrc + 2048); cpasync16(kdst[1] + 16, ksrc + 2052);
    if (tid < 128) cpasync16(vdst[1], vsrc + 512);
    CP_COMMIT();

    #pragma unroll 1
    for (int c = 0; c < 64; c++) {
        if (c + 1 < 64) { CP_WAIT1(); } else { CP_WAIT0(); }
        __syncthreads();
        if (c + 2 < 64) {
            int st = (c + 2) % 3;
            const uint32_t* kp = ksrc + (size_t)(c+2)*2048;
            const uint32_t* vp = vsrc + (size_t)(c+2)*512;
            cpasync16(kdst[st], kp); cpasync16(kdst[st] + 16, kp + 4);
            if (tid < 128) cpasync16(vdst[st], vp);
            CP_COMMIT();
        }
        int st = c % 3;
        const uint32_t* Kc = smu + FKOFFU(st);
        const uint32_t* Vc = smu + FVOFFU(st);

        #pragma unroll
        for (int ks = 0; ks < 4; ks++) {
            float s0[4] = {0.f,0.f,0.f,0.f};
            float s1[4] = {0.f,0.f,0.f,0.f};
            const uint32_t* kr0 = Kc + (ks*16 + g)*KSTRU;
            const uint32_t* kr1 = kr0 + 8*KSTRU;
            #pragma unroll
            for (int kd = 0; kd < 4; kd++) {
                uint2 k0 = *(const uint2*)(kr0 + kd*8 + 2*tg);
                uint2 k1 = *(const uint2*)(kr1 + kd*8 + 2*tg);
                mma16bf(s0, qa[kd], k0.x, k0.y);
                mma16bf(s1, qa[kd], k1.x, k1.y);
            }
            float u00 = ex2f(s0[0]) - 1.f, u01 = ex2f(s0[1]) - 1.f;
            float u02 = ex2f(s0[2]) - 1.f, u03 = ex2f(s0[3]) - 1.f;
            float u10 = ex2f(s1[0]) - 1.f, u11 = ex2f(s1[1]) - 1.f;
            float u12 = ex2f(s1[2]) - 1.f, u13 = ex2f(s1[3]) - 1.f;
            l0 += (u00 + u01) + (u10 + u11);
            l1 += (u02 + u03) + (u12 + u13);
            uint32_t ap[4];
            ap[0] = f2bf2(u00, u01);
            ap[1] = f2bf2(u02, u03);
            ap[2] = f2bf2(u10, u11);
            ap[3] = f2bf2(u12, u13);
            const uint32_t* vr0 = Vc + (ks*8 + tg)*24;
            const uint32_t* vr1 = Vc + (ks*8 + tg + 4)*24;
            mma16bf(Ofr[0], ap, vr0[g],     vr1[g]);
            mma16bf(Ofr[1], ap, vr0[g + 8], vr1[g + 8]);
        }
    }
    l0 += __shfl_xor_sync(0xffffffffu, l0, 1);
    l0 += __shfl_xor_sync(0xffffffffu, l0, 2);
    l1 += __shfl_xor_sync(0xffffffffu, l1, 1);
    l1 += __shfl_xor_sync(0xffffffffu, l1, 2);

    float inv0 = 1.f / (4096.f + l0), inv1 = 1.f / (4096.f + l1);
    int n_g  = qt*128 + q0 + g;
    int n_g8 = n_g + 8;
    float* op0 = out + ((size_t)b*NTOK + h*512 + (n_g  >> 3))*640 + 512 + (n_g  & 7)*16;
    float* op1 = out + ((size_t)b*NTOK + h*512 + (n_g8 >> 3))*640 + 512 + (n_g8 & 7)*16;
    #pragma unroll
    for (int nt = 0; nt < 2; nt++) {
        int cbase = nt*8 + 2*tg;
        float2 cs = *(const float2*)(g_Vcs + bh*16 + cbase);
        float2 a, c2;
        a.x  = (cs.x + Ofr[nt][0])*inv0; a.y  = (cs.y + Ofr[nt][1])*inv0;
        c2.x = (cs.x + Ofr[nt][2])*inv1; c2.y = (cs.y + Ofr[nt][3])*inv1;
        *(float2*)(op0 + cbase) = a;
        *(float2*)(op1 + cbase) = c2;
    }
}

// =================== launch (sequential, R11 order) ===================
extern "C" void kernel_launch(void* const* d_in, const int* in_sizes, int n_in,
                              void* d_out, int out_size)
{
    const float* s_in = (const float*)d_in[0];
    const float* h_in = (const float*)d_in[1];
    const float* sh   = (const float*)d_in[2];
    const float* t1   = (const float*)d_in[3];
    const float* t2   = (const float*)d_in[4];
    const float* Wqc  = (const float*)d_in[5];
    const float* Wqs  = (const float*)d_in[6];
    const float* Wkc  = (const float*)d_in[7];
    const float* Wvc  = (const float*)d_in[8];
    const float* Wks  = (const float*)d_in[9];
    const float* Wvs  = (const float*)d_in[10];
    float* out = (float*)d_out;

    cudaFuncSetAttribute(flash_mma, cudaFuncAttributeMaxDynamicSharedMemorySize, FSMEM);
    cudaFuncSetAttribute(gemm_proj_tc, cudaFuncAttributeMaxDynamicSharedMemorySize, GSMEM);
    cudaFuncSetAttribute(gemm_vs_tc, cudaFuncAttributeMaxDynamicSharedMemorySize, GSMEM);

    prep<<<(SEGT + 255) / 256, 256>>>(
        (const float4*)s_in, (const float4*)sh, (const float4*)h_in,
        (const float4*)Wqc, (const float4*)Wqs, (const float4*)Wkc,
        (const float4*)Wvc, (const float4*)Wks, (const float4*)Wvs);
    gemm_proj_tc<<<dim3(20,64), 256, GSMEM>>>();
    gemm_vs_tc<<<64, 256, GSMEM>>>();
    repack_v<<<dim3(8,16), 256>>>();
    vcs_reduce<<<1, 256>>>();
    flash_mma<<<dim3(32,16), 256, FSMEM>>>(t2, out);
    ca_scores<<<dim3(16,16), 256>>>();
    ca_reduce<<<16, 64>>>(t1);
    ca_out<<<dim3(64,16), 256>>>(out);
}

// round 16
// speedup vs baseline: 1.2201x; 1.1375x over previous
#include <cuda_runtime.h>
#include <math.h>
#include <stdint.h>

#define NB 2
#define NTOK 4096

__device__ float g_Pqc[8192*512];
__device__ float g_Pqs[8192*512];
__device__ float g_Pkc[8192*512];
__device__ float g_Pvc[8192*512];
__device__ uint32_t g_PksU[8192*256];   // K_s as bf16x2 pairs, slot-permuted
__device__ float g_Pvs[8192*128];       // V_s fp32 (unrounded)
__device__ uint32_t g_Vp[16*2048*16];   // V_s as bf16x2 key-pairs
__device__ float g_Vcs[16*16];
__device__ float g_VcsP[128*16];
__device__ float g_Sca[16*16*64*64];
__device__ float g_Pca[16*64*64];
// bf16-packed inputs (k-pairs in u32) for logit-path projections
__device__ uint32_t g_bs  [8192*256];
__device__ uint32_t g_bsh [8192*256];
__device__ uint32_t g_bWqs[512*256];
__device__ uint32_t g_bWkc[512*256];
__device__ uint32_t g_bWks[512*256];
__device__ uint32_t g_bWqc[512*256];
// tf32 inputs for value-path projections
__device__ float g_tsh [8192*512];
__device__ float g_th  [8192*128];
__device__ float g_tWvc[512*512];
__device__ float g_tWvs[128*128];

// =================== helpers ===================
__device__ __forceinline__ uint32_t f2tf(float x) {
    uint32_t r; asm("cvt.rna.tf32.f32 %0, %1;" : "=r"(r) : "f"(x)); return r;
}
__device__ __forceinline__ uint32_t f2bf2(float lo, float hi) {
    uint32_t r; asm("cvt.rn.bf16x2.f32 %0, %1, %2;" : "=r"(r) : "f"(hi), "f"(lo)); return r;
}
__device__ __forceinline__ float ex2f(float x) {
    float r; asm("ex2.approx.ftz.f32 %0, %1;" : "=f"(r) : "f"(x)); return r;
}
__device__ __forceinline__ void mma8(float* d, const uint32_t* a, uint32_t b0, uint32_t b1) {
    asm volatile(
        "mma.sync.aligned.m16n8k8.row.col.f32.tf32.tf32.f32 "
        "{%0,%1,%2,%3},{%4,%5,%6,%7},{%8,%9},{%0,%1,%2,%3};"
        : "+f"(d[0]), "+f"(d[1]), "+f"(d[2]), "+f"(d[3])
        : "r"(a[0]), "r"(a[1]), "r"(a[2]), "r"(a[3]), "r"(b0), "r"(b1));
}
__device__ __forceinline__ void mma16bf(float* d, const uint32_t* a, uint32_t b0, uint32_t b1) {
    asm volatile(
        "mma.sync.aligned.m16n8k16.row.col.f32.bf16.bf16.f32 "
        "{%0,%1,%2,%3},{%4,%5,%6,%7},{%8,%9},{%0,%1,%2,%3};"
        : "+f"(d[0]), "+f"(d[1]), "+f"(d[2]), "+f"(d[3])
        : "r"(a[0]), "r"(a[1]), "r"(a[2]), "r"(a[3]), "r"(b0), "r"(b1));
}
__device__ __forceinline__ uint32_t smem_u32(const void* p) {
    uint32_t a;
    asm("{ .reg .u64 t; cvta.to.shared.u64 t, %1; cvt.u32.u64 %0, t; }" : "=r"(a) : "l"(p));
    return a;
}
__device__ __forceinline__ void cpasync16(uint32_t dst, const void* src) {
    asm volatile("cp.async.ca.shared.global [%0], [%1], 16;" :: "r"(dst), "l"(src));
}
#define CP_COMMIT() asm volatile("cp.async.commit_group;" ::: "memory")
#define CP_WAIT1()  asm volatile("cp.async.wait_group 1;" ::: "memory")
#define CP_WAIT0()  asm volatile("cp.async.wait_group 0;" ::: "memory")

// =================== prep: bf16-pack logit inputs, tf32-round value inputs ===================
// units of 8 floats
#define SEG0 524288    // s      -> bf16
#define SEG1 1048576   // sh     -> bf16 + tf32
#define SEG2 1179648   // h      -> tf32
#define SEG3 1212416   // Wqs    -> bf16
#define SEG4 1245184   // Wkc    -> bf16
#define SEG5 1277952   // Wks    -> bf16
#define SEG6 1310720   // Wqc    -> bf16
#define SEG7 1343488   // Wvc    -> tf32
#define SEGT 1345536   // Wvs    -> tf32
__global__ __launch_bounds__(256) void prep(
    const float4* __restrict__ s, const float4* __restrict__ sh, const float4* __restrict__ h,
    const float4* __restrict__ wqc, const float4* __restrict__ wqs, const float4* __restrict__ wkc,
    const float4* __restrict__ wvc, const float4* __restrict__ wks, const float4* __restrict__ wvs)
{
    int i = blockIdx.x * blockDim.x + threadIdx.x;
    if (i >= SEGT) return;
    const float4* src; int off; int kind;   // 0=bf16, 1=tf32, 2=both
    uint32_t* bdst = 0; float4* tdst = 0;
    if      (i < SEG0) { src = s;   off = i;        kind = 0; bdst = g_bs; }
    else if (i < SEG1) { src = sh;  off = i - SEG0; kind = 2; bdst = g_bsh; tdst = (float4*)g_tsh; }
    else if (i < SEG2) { src = h;   off = i - SEG1; kind = 1; tdst = (float4*)g_th; }
    else if (i < SEG3) { src = wqs; off = i - SEG2; kind = 0; bdst = g_bWqs; }
    else if (i < SEG4) { src = wkc; off = i - SEG3; kind = 0; bdst = g_bWkc; }
    else if (i < SEG5) { src = wks; off = i - SEG4; kind = 0; bdst = g_bWks; }
    else if (i < SEG6) { src = wqc; off = i - SEG5; kind = 0; bdst = g_bWqc; }
    else if (i < SEG7) { src = wvc; off = i - SEG6; kind = 1; tdst = (float4*)g_tWvc; }
    else               { src = wvs; off = i - SEG7; kind = 1; tdst = (float4*)g_tWvs; }
    float4 a = src[2*off], b = src[2*off + 1];
    if (kind != 1) {
        uint4 pk;
        pk.x = f2bf2(a.x, a.y); pk.y = f2bf2(a.z, a.w);
        pk.z = f2bf2(b.x, b.y); pk.w = f2bf2(b.z, b.w);
        *(uint4*)(bdst + 4*off) = pk;
    }
    if (kind != 0) {
        tdst[2*off]     = make_float4(__uint_as_float(f2tf(a.x)), __uint_as_float(f2tf(a.y)),
                                      __uint_as_float(f2tf(a.z)), __uint_as_float(f2tf(a.w)));
        tdst[2*off + 1] = make_float4(__uint_as_float(f2tf(b.x)), __uint_as_float(f2tf(b.y)),
                                      __uint_as_float(f2tf(b.z)), __uint_as_float(f2tf(b.w)));
    }
}

// =========== bf16 TC GEMM (logit projections): K-chunk 16, 3-stage, stride-12 ===========
#define BSTR 12
#define BSTG (128*BSTR)          // 1536 u32 per stage per matrix

__global__ __launch_bounds__(256, 2) void gemm_proj_bf()
{
    __shared__ uint32_t smq[3*BSTG*2];   // 36864 B
    int job = blockIdx.x >> 2;
    int ot  = blockIdx.x & 3;
    int m0  = blockIdx.y << 7;
    const uint32_t* A; const uint32_t* W; float* C; int mode;
    switch (job) {
        case 0:  A = g_bsh; W = g_bWqs; C = g_Pqs; mode = 0; break;
        case 1:  A = g_bsh; W = g_bWkc; C = g_Pkc; mode = 0; break;
        case 2:  A = g_bsh; W = g_bWks; C = 0;     mode = 2; break;
        default: A = g_bs;  W = g_bWqc; C = g_Pqc; mode = 0; break;
    }
    uint32_t* sA = smq;
    uint32_t* sW = smq + 3*BSTG;
    int tid = threadIdx.x, w = tid >> 5, lane = tid & 31;
    int g = lane >> 2, tg = lane & 3;
    int wm = w >> 2, wn = w & 3;
    int pr = tid >> 1, pq = (tid & 1) << 2;      // copy: row pr, 4 u32 at pq
    const uint32_t* Ap = A + (size_t)(m0 + pr)*256 + pq;
    const uint32_t* Wp = W + (size_t)(ot*128 + pr)*256 + pq;
    uint32_t sAb[3], sWb[3];
    #pragma unroll
    for (int st = 0; st < 3; st++) {
        sAb[st] = smem_u32(sA + st*BSTG + pr*BSTR + pq);
        sWb[st] = smem_u32(sW + st*BSTG + pr*BSTR + pq);
    }

    float acc[4][4][4];
    #pragma unroll
    for (int mt = 0; mt < 4; mt++)
        #pragma unroll
        for (int nt = 0; nt < 4; nt++)
            #pragma unroll
            for (int e = 0; e < 4; e++) acc[mt][nt][e] = 0.f;

    // prologue: chunks 0,1
    cpasync16(sAb[0], Ap);     cpasync16(sWb[0], Wp);
    CP_COMMIT();
    cpasync16(sAb[1], Ap + 8); cpasync16(sWb[1], Wp + 8);
    CP_COMMIT();

    #pragma unroll 1
    for (int c = 0; c < 32; c++) {
        if (c + 1 < 32) { CP_WAIT1(); } else { CP_WAIT0(); }
        __syncthreads();
        if (c + 2 < 32) {
            int st = (c + 2) % 3;
            cpasync16(sAb[st], Ap + (c+2)*8);
            cpasync16(sWb[st], Wp + (c+2)*8);
            CP_COMMIT();
        }
        int st = c % 3;
        const uint32_t* cA = sA + st*BSTG;
        const uint32_t* cW = sW + st*BSTG;
        uint32_t af[4][4], bf[4][2];
        #pragma unroll
        for (int mt = 0; mt < 4; mt++) {
            int rb = wm*64 + mt*16;
            af[mt][0] = cA[(rb+g  )*BSTR + tg];
            af[mt][1] = cA[(rb+g+8)*BSTR + tg];
            af[mt][2] = cA[(rb+g  )*BSTR + tg + 4];
            af[mt][3] = cA[(rb+g+8)*BSTR + tg + 4];
        }
        #pragma unroll
        for (int nt = 0; nt < 4; nt++) {
            int rb = wn*32 + nt*8 + g;
            bf[nt][0] = cW[rb*BSTR + tg];
            bf[nt][1] = cW[rb*BSTR + tg + 4];
        }
        #pragma unroll
        for (int mt = 0; mt < 4; mt++)
            #pragma unroll
            for (int nt = 0; nt < 4; nt++)
                mma16bf(acc[mt][nt], af[mt], bf[nt][0], bf[nt][1]);
    }
    int o0 = ot << 7;
    #pragma unroll
    for (int mt = 0; mt < 4; mt++) {
        int r = m0 + wm*64 + mt*16 + g;
        #pragma unroll
        for (int nt = 0; nt < 4; nt++) {
            float v0 = acc[mt][nt][0], v1 = acc[mt][nt][1];
            float v2 = acc[mt][nt][2], v3 = acc[mt][nt][3];
            if (mode == 2) {
                uint32_t lo = f2bf2(v0, v1);
                uint32_t hi = f2bf2(v2, v3);
                int c0  = o0 + wn*32 + nt*8 + 2*tg;
                int blk = c0 >> 6;
                int d   = c0 & 63;
                int slot = (nt & 1) ? (2*tg + 1) : (2*tg);
                uint32_t* kp = g_PksU + (size_t)r*256 + blk*32 + (d >> 4)*8 + slot;
                kp[0]     = lo;
                kp[8*256] = hi;
            } else {
                float* cp = C + (size_t)r*512 + o0 + wn*32 + nt*8;
                *(float2*)(cp + 2*tg)         = make_float2(v0, v1);
                *(float2*)(cp + 8*512 + 2*tg) = make_float2(v2, v3);
            }
        }
    }
}

// =================== tf32 TC GEMM (value projections, R11 proven) ===================
#define GSTG 2560
#define GSMEM (3*GSTG*2*4)

template<int K, int O>
__device__ __forceinline__ void gemm_tc_tile(const float* __restrict__ A,
                                             const float* __restrict__ W,
                                             float* __restrict__ C,
                                             int m0, int o0, float* dynsm)
{
    const int NC = K / 16;
    float* sA = dynsm;
    float* sW = dynsm + 3*GSTG;
    int tid = threadIdx.x, w = tid >> 5, lane = tid & 31;
    int g = lane >> 2, tg = lane & 3;
    int wm = w >> 2, wn = w & 3;
    int pr = tid >> 1, pc = (tid & 1) << 3;
    const float* Ap = A + (size_t)(m0 + pr) * K + pc;
    const float* Wp = W + (size_t)(o0 + pr) * K + pc;
    uint32_t sAb[3], sWb[3];
    #pragma unroll
    for (int st = 0; st < 3; st++) {
        sAb[st] = smem_u32(sA + st*GSTG + pr*20 + pc);
        sWb[st] = smem_u32(sW + st*GSTG + pr*20 + pc);
    }
    float acc[4][4][4];
    #pragma unroll
    for (int mt = 0; mt < 4; mt++)
        #pragma unroll
        for (int nt = 0; nt < 4; nt++)
            #pragma unroll
            for (int e = 0; e < 4; e++) acc[mt][nt][e] = 0.f;

    cpasync16(sAb[0],      Ap);      cpasync16(sAb[0] + 16, Ap + 4);
    cpasync16(sWb[0],      Wp);      cpasync16(sWb[0] + 16, Wp + 4);
    CP_COMMIT();
    cpasync16(sAb[1],      Ap + 16); cpasync16(sAb[1] + 16, Ap + 20);
    cpasync16(sWb[1],      Wp + 16); cpasync16(sWb[1] + 16, Wp + 20);
    CP_COMMIT();

    #pragma unroll 1
    for (int c = 0; c < NC; c++) {
        if (c + 1 < NC) { CP_WAIT1(); } else { CP_WAIT0(); }
        __syncthreads();
        if (c + 2 < NC) {
            int st = (c + 2) % 3;
            const float* ap = Ap + (c+2)*16;
            const float* wp = Wp + (c+2)*16;
            cpasync16(sAb[st],      ap); cpasync16(sAb[st] + 16, ap + 4);
            cpasync16(sWb[st],      wp); cpasync16(sWb[st] + 16, wp + 4);
            CP_COMMIT();
        }
        int st = c % 3;
        const uint32_t* cA = (const uint32_t*)(sA + st*GSTG);
        const uint32_t* cW = (const uint32_t*)(sW + st*GSTG);
        #pragma unroll
        for (int ks = 0; ks < 2; ks++) {
            uint32_t af[4][4], bf[4][2];
            #pragma unroll
            for (int mt = 0; mt < 4; mt++) {
                int rb = wm*64 + mt*16;
                af[mt][0] = cA[(rb+g  )*20 + ks*8 + tg];
                af[mt][1] = cA[(rb+g+8)*20 + ks*8 + tg];
                af[mt][2] = cA[(rb+g  )*20 + ks*8 + tg + 4];
                af[mt][3] = cA[(rb+g+8)*20 + ks*8 + tg + 4];
            }
            #pragma unroll
            for (int nt = 0; nt < 4; nt++) {
                int rb = wn*32 + nt*8 + g;
                bf[nt][0] = cW[rb*20 + ks*8 + tg];
                bf[nt][1] = cW[rb*20 + ks*8 + tg + 4];
            }
            #pragma unroll
            for (int mt = 0; mt < 4; mt++)
                #pragma unroll
                for (int nt = 0; nt < 4; nt++)
                    mma8(acc[mt][nt], af[mt], bf[nt][0], bf[nt][1]);
        }
    }
    #pragma unroll
    for (int mt = 0; mt < 4; mt++) {
        int r = m0 + wm*64 + mt*16 + g;
        #pragma unroll
        for (int nt = 0; nt < 4; nt++) {
            float* cp = C + (size_t)r*O + o0 + wn*32 + nt*8;
            *(float2*)(cp + 2*tg)       = make_float2(acc[mt][nt][0], acc[mt][nt][1]);
            *(float2*)(cp + 8*O + 2*tg) = make_float2(acc[mt][nt][2], acc[mt][nt][3]);
        }
    }
}

__global__ __launch_bounds__(256, 2) void gemm_vc_tc()
{
    extern __shared__ float gdsm[];
    gemm_tc_tile<512,512>(g_tsh, g_tWvc, g_Pvc, blockIdx.y << 7, blockIdx.x << 7, gdsm);
}

__global__ __launch_bounds__(256, 2) void gemm_vs_tc()
{
    extern __shared__ float gdsm[];
    gemm_tc_tile<128,128>(g_th, g_tWvs, g_Pvs, blockIdx.x << 7, 0, gdsm);
}

// ============ repack V_s (sliced) + column-sum reduce ============
__global__ __launch_bounds__(256) void repack_v()
{
    __shared__ float4 red[256];
    int slice = blockIdx.x;
    int bh    = blockIdx.y;
    int b = bh >> 3, h = bh & 7;
    const float* Vb = g_Pvs + ((size_t)b*NTOK + h*512)*128;
    uint32_t* Vp = g_Vp + (size_t)bh*32768;
    int tid = threadIdx.x;
    float4 part = make_float4(0.f, 0.f, 0.f, 0.f);
    #pragma unroll
    for (int it = 0; it < 4; it++) {
        int i = slice*1024 + it*256 + tid;
        int key2 = i >> 2, cg = (i & 3) << 2;
        float4 v0 = *(const float4*)(Vb + (size_t)(2*key2)*16 + cg);
        float4 v1 = *(const float4*)(Vb + (size_t)(2*key2+1)*16 + cg);
        uint4 pk;
        pk.x = f2bf2(v0.x, v1.x);
        pk.y = f2bf2(v0.y, v1.y);
        pk.z = f2bf2(v0.z, v1.z);
        pk.w = f2bf2(v0.w, v1.w);
        *(uint4*)(Vp + (size_t)key2*16 + cg) = pk;
        part.x += v0.x + v1.x;
        part.y += v0.y + v1.y;
        part.z += v0.z + v1.z;
        part.w += v0.w + v1.w;
    }
    red[tid] = part;
    __syncthreads();
    if (tid < 4) {
        float4 ssum = make_float4(0.f, 0.f, 0.f, 0.f);
        for (int t = tid; t < 256; t += 4) {
            float4 v = red[t];
            ssum.x += v.x; ssum.y += v.y; ssum.z += v.z; ssum.w += v.w;
        }
        *(float4*)(g_VcsP + (bh*8 + slice)*16 + tid*4) = ssum;
    }
}

__global__ void vcs_reduce()
{
    int tid = threadIdx.x;
    int bh = tid >> 4, col = tid & 15;
    float s = 0.f;
    #pragma unroll
    for (int p = 0; p < 8; p++)
        s += g_VcsP[(bh*8 + p)*16 + col];
    g_Vcs[bh*16 + col] = s;
}

// =================== channel attention (fp32, unchanged) ===================
__global__ __launch_bounds__(256) void ca_scores()
{
    __shared__ float Qs[32][68];
    __shared__ float Ks[32][68];
    int slice = blockIdx.x;
    int bh    = blockIdx.y;
    int b = bh >> 3, h = bh & 7;
    const float* Qc = g_Pqc + ((size_t)b*NTOK + h*512) * 512;
    const float* Kc = g_Pkc + ((size_t)b*NTOK + h*512) * 512;
    int tid = threadIdx.x;
    int lr = tid >> 3, lc = (tid & 7) << 3;
    int i0 = (tid >> 4) << 2, j0 = (tid & 15) << 2;
    float acc[4][4];
    #pragma unroll
    for (int i = 0; i < 4; i++)
        #pragma unroll
        for (int j = 0; j < 4; j++) acc[i][j] = 0.f;
    #pragma unroll 1
    for (int nt = 0; nt < 8; nt++) {
        int nb = slice*256 + (nt << 5);
        const float* qp = Qc + (size_t)(nb + lr)*64 + lc;
        const float* kp = Kc + (size_t)(nb + lr)*64 + lc;
        float4 q0 = *(const float4*)qp, q1 = *(const float4*)(qp+4);
        float4 k0 = *(const float4*)kp, k1 = *(const float4*)(kp+4);
        __syncthreads();
        *(float4*)&Qs[lr][lc] = q0; *(float4*)&Qs[lr][lc+4] = q1;
        *(float4*)&Ks[lr][lc] = k0; *(float4*)&Ks[lr][lc+4] = k1;
        __syncthreads();
        #pragma unroll 8
        for (int nn = 0; nn < 32; nn++) {
            float4 q = *(const float4*)&Qs[nn][i0];
            float4 k = *(const float4*)&Ks[nn][j0];
            float qa[4] = {q.x,q.y,q.z,q.w};
            float ka[4] = {k.x,k.y,k.z,k.w};
            #pragma unroll
            for (int i = 0; i < 4; i++)
                #pragma unroll
                for (int j = 0; j < 4; j++)
                    acc[i][j] = fmaf(qa[i], ka[j], acc[i][j]);
        }
    }
    float* dst = g_Sca + ((size_t)(bh*16 + slice)*64)*64;
    #pragma unroll
    for (int i = 0; i < 4; i++)
        *(float4*)&dst[(i0+i)*64 + j0] = make_float4(acc[i][0],acc[i][1],acc[i][2],acc[i][3]);
}

__global__ void ca_reduce(const float* __restrict__ temp)
{
    int bh = blockIdx.x;
    int h  = bh & 7;
    int i  = threadIdx.x;
    float scale = 0.125f * temp[h];
    float row[64];
    #pragma unroll
    for (int j = 0; j < 64; j++) {
        float s = 0.f;
        #pragma unroll
        for (int p = 0; p < 16; p++)
            s += g_Sca[((size_t)(bh*16+p)*64 + i)*64 + j];
        row[j] = s * scale;
    }
    float m = row[0];
    #pragma unroll
    for (int j = 1; j < 64; j++) m = fmaxf(m, row[j]);
    float sum = 0.f;
    #pragma unroll
    for (int j = 0; j < 64; j++) { row[j] = __expf(row[j]-m); sum += row[j]; }
    float inv = 1.f / sum;
    #pragma unroll
    for (int j = 0; j < 64; j++)
        g_Pca[((size_t)bh*64 + i)*64 + j] = row[j]*inv;
}

__global__ __launch_bounds__(256) void ca_out(float* __restrict__ out)
{
    __shared__ float Pts[64][68];
    __shared__ float Vt[64][68];
    int mt = blockIdx.x;
    int bh = blockIdx.y;
    int b = bh >> 3, h = bh & 7;
    int tid = threadIdx.x;
    {
        int i  = tid & 63;
        int jc = (tid >> 6) << 4;
        const float* pp = g_Pca + ((size_t)bh*64 + i)*64 + jc;
        #pragma unroll
        for (int t = 0; t < 4; t++) {
            float4 v = *(const float4*)(pp + t*4);
            Pts[jc+t*4+0][i] = v.x; Pts[jc+t*4+1][i] = v.y;
            Pts[jc+t*4+2][i] = v.z; Pts[jc+t*4+3][i] = v.w;
        }
    }
    {
        int mm = tid & 63;
        int jc = (tid >> 6) << 4;
        const float* vp = g_Pvc + ((size_t)b*NTOK + h*512)*512 + (size_t)(mt*64 + mm)*64 + jc;
        #pragma unroll
        for (int t = 0; t < 4; t++) {
            float4 v = *(const float4*)(vp + t*4);
            Vt[jc+t*4+0][mm] = v.x; Vt[jc+t*4+1][mm] = v.y;
            Vt[jc+t*4+2][mm] = v.z; Vt[jc+t*4+3][mm] = v.w;
        }
    }
    __syncthreads();
    int i0 = (tid >> 4) << 2, m0 = (tid & 15) << 2;
    float acc[4][4];
    #pragma unroll
    for (int i = 0; i < 4; i++)
        #pragma unroll
        for (int j = 0; j < 4; j++) acc[i][j] = 0.f;
    #pragma unroll 8
    for (int j = 0; j < 64; j++) {
        float4 p = *(const float4*)&Pts[j][i0];
        float4 v = *(const float4*)&Vt[j][m0];
        float pa[4] = {p.x,p.y,p.z,p.w};
        float va[4] = {v.x,v.y,v.z,v.w};
        #pragma unroll
        for (int i = 0; i < 4; i++)
            #pragma unroll
            for (int m = 0; m < 4; m++)
                acc[i][m] = fmaf(pa[i], va[m], acc[i][m]);
    }
    int rowoff  = mt >> 3;
    int colbase = (mt & 7)*64 + m0;
    #pragma unroll
    for (int i = 0; i < 4; i++) {
        int row = h*512 + (i0+i)*8 + rowoff;
        float* op = out + ((size_t)b*NTOK + row)*640 + colbase;
        *(float4*)op = make_float4(acc[i][0],acc[i][1],acc[i][2],acc[i][3]);
    }
}

// ====== spatial flash: all-bf16 mma, 1+u softmax decomposition (R11) ======
#define KSTRU 40
#define FKOFFU(s) ((s)*2560)
#define FVOFFU(s) (7680 + (s)*768)
#define FSMEM (9984 * 4)

__global__ __launch_bounds__(256, 2) void flash_mma(const float* __restrict__ t2,
                                                    float* __restrict__ out)
{
    extern __shared__ float sm[];
    uint32_t* smu = (uint32_t*)sm;
    int tid = threadIdx.x, w = tid >> 5, lane = tid & 31;
    int g = lane >> 2, tg = lane & 3;
    int qt = blockIdx.x, bh = blockIdx.y;
    int b = bh >> 3, h = bh & 7;
    const float*    Qb  = g_Pqs  + ((size_t)b*NTOK + h*512)*512;
    const uint32_t* KbU = g_PksU + ((size_t)b*NTOK + h*512)*256;
    const uint32_t* Vpg = g_Vp + (size_t)bh*32768;
    float qscale = 0.125f * t2[h] * 1.4426950408889634f;

    int kr = tid >> 2, kq = tid & 3;
    uint32_t kdst[3], vdst[3];
    #pragma unroll
    for (int st = 0; st < 3; st++) {
        kdst[st] = smem_u32(smu + FKOFFU(st) + kr*KSTRU + kq*8);
        vdst[st] = smem_u32(smu + FVOFFU(st) + kr*24 + kq*4);
    }
    const uint32_t* ksrc = KbU + (size_t)kr*32 + kq*8;
    const uint32_t* vsrc = Vpg + (size_t)kr*16 + kq*4;

    int q0 = w << 4;
    uint32_t qa[4][4];
    {
        const float* qr0 = Qb + (size_t)(qt*128 + q0 + g)*64;
        const float* qr1 = qr0 + 8*64;
        #pragma unroll
        for (int kd = 0; kd < 4; kd++) {
            int d0 = kd*16 + 2*tg;
            qa[kd][0] = f2bf2(qr0[d0]*qscale,   qr0[d0+1]*qscale);
            qa[kd][1] = f2bf2(qr1[d0]*qscale,   qr1[d0+1]*qscale);
            qa[kd][2] = f2bf2(qr0[d0+8]*qscale, qr0[d0+9]*qscale);
            qa[kd][3] = f2bf2(qr1[d0+8]*qscale, qr1[d0+9]*qscale);
        }
    }

    float Ofr[2][4];
    #pragma unroll
    for (int n = 0; n < 2; n++)
        #pragma unroll
        for (int e = 0; e < 4; e++) Ofr[n][e] = 0.f;
    float l0 = 0.f, l1 = 0.f;

    cpasync16(kdst[0], ksrc); cpasync16(kdst[0] + 16, ksrc + 4);
    if (tid < 128) cpasync16(vdst[0], vsrc);
    CP_COMMIT();
    cpasync16(kdst[1], ksrc + 2048); cpasync16(kdst[1] + 16, ksrc + 2052);
    if (tid < 128) cpasync16(vdst[1], vsrc + 512);
    CP_COMMIT();

    #pragma unroll 1
    for (int c = 0; c < 64; c++) {
        if (c + 1 < 64) { CP_WAIT1(); } else { CP_WAIT0(); }
        __syncthreads();
        if (c + 2 < 64) {
            int st = (c + 2) % 3;
            const uint32_t* kp = ksrc + (size_t)(c+2)*2048;
            const uint32_t* vp = vsrc + (size_t)(c+2)*512;
            cpasync16(kdst[st], kp); cpasync16(kdst[st] + 16, kp + 4);
            if (tid < 128) cpasync16(vdst[st], vp);
            CP_COMMIT();
        }
        int st = c % 3;
        const uint32_t* Kc = smu + FKOFFU(st);
        const uint32_t* Vc = smu + FVOFFU(st);

        #pragma unroll
        for (int ks = 0; ks < 4; ks++) {
            float s0[4] = {0.f,0.f,0.f,0.f};
            float s1[4] = {0.f,0.f,0.f,0.f};
            const uint32_t* kr0 = Kc + (ks*16 + g)*KSTRU;
            const uint32_t* kr1 = kr0 + 8*KSTRU;
            #pragma unroll
            for (int kd = 0; kd < 4; kd++) {
                uint2 k0 = *(const uint2*)(kr0 + kd*8 + 2*tg);
                uint2 k1 = *(const uint2*)(kr1 + kd*8 + 2*tg);
                mma16bf(s0, qa[kd], k0.x, k0.y);
                mma16bf(s1, qa[kd], k1.x, k1.y);
            }
            float u00 = ex2f(s0[0]) - 1.f, u01 = ex2f(s0[1]) - 1.f;
            float u02 = ex2f(s0[2]) - 1.f, u03 = ex2f(s0[3]) - 1.f;
            float u10 = ex2f(s1[0]) - 1.f, u11 = ex2f(s1[1]) - 1.f;
            float u12 = ex2f(s1[2]) - 1.f, u13 = ex2f(s1[3]) - 1.f;
            l0 += (u00 + u01) + (u10 + u11);
            l1 += (u02 + u03) + (u12 + u13);
            uint32_t ap[4];
            ap[0] = f2bf2(u00, u01);
            ap[1] = f2bf2(u02, u03);
            ap[2] = f2bf2(u10, u11);
            ap[3] = f2bf2(u12, u13);
            const uint32_t* vr0 = Vc + (ks*8 + tg)*24;
            const uint32_t* vr1 = Vc + (ks*8 + tg + 4)*24;
            mma16bf(Ofr[0], ap, vr0[g],     vr1[g]);
            mma16bf(Ofr[1], ap, vr0[g + 8], vr1[g + 8]);
        }
    }
    l0 += __shfl_xor_sync(0xffffffffu, l0, 1);
    l0 += __shfl_xor_sync(0xffffffffu, l0, 2);
    l1 += __shfl_xor_sync(0xffffffffu, l1, 1);
    l1 += __shfl_xor_sync(0xffffffffu, l1, 2);

    float inv0 = 1.f / (4096.f + l0), inv1 = 1.f / (4096.f + l1);
    int n_g  = qt*128 + q0 + g;
    int n_g8 = n_g + 8;
    float* op0 = out + ((size_t)b*NTOK + h*512 + (n_g  >> 3))*640 + 512 + (n_g  & 7)*16;
    float* op1 = out + ((size_t)b*NTOK + h*512 + (n_g8 >> 3))*640 + 512 + (n_g8 & 7)*16;
    #pragma unroll
    for (int nt = 0; nt < 2; nt++) {
        int cbase = nt*8 + 2*tg;
        float2 cs = *(const float2*)(g_Vcs + bh*16 + cbase);
        float2 a, c2;
        a.x  = (cs.x + Ofr[nt][0])*inv0; a.y  = (cs.y + Ofr[nt][1])*inv0;
        c2.x = (cs.x + Ofr[nt][2])*inv1; c2.y = (cs.y + Ofr[nt][3])*inv1;
        *(float2*)(op0 + cbase) = a;
        *(float2*)(op1 + cbase) = c2;
    }
}

// =================== launch ===================
extern "C" void kernel_launch(void* const* d_in, const int* in_sizes, int n_in,
                              void* d_out, int out_size)
{
    const float* s_in = (const float*)d_in[0];
    const float* h_in = (const float*)d_in[1];
    const float* sh   = (const float*)d_in[2];
    const float* t1   = (const float*)d_in[3];
    const float* t2   = (const float*)d_in[4];
    const float* Wqc  = (const float*)d_in[5];
    const float* Wqs  = (const float*)d_in[6];
    const float* Wkc  = (const float*)d_in[7];
    const float* Wvc  = (const float*)d_in[8];
    const float* Wks  = (const float*)d_in[9];
    const float* Wvs  = (const float*)d_in[10];
    float* out = (float*)d_out;

    cudaFuncSetAttribute(flash_mma, cudaFuncAttributeMaxDynamicSharedMemorySize, FSMEM);
    cudaFuncSetAttribute(gemm_vc_tc, cudaFuncAttributeMaxDynamicSharedMemorySize, GSMEM);
    cudaFuncSetAttribute(gemm_vs_tc, cudaFuncAttributeMaxDynamicSharedMemorySize, GSMEM);

    prep<<<(SEGT + 255) / 256, 256>>>(
        (const float4*)s_in, (const float4*)sh, (const float4*)h_in,
        (const float4*)Wqc, (const float4*)Wqs, (const float4*)Wkc,
        (const float4*)Wvc, (const float4*)Wks, (const float4*)Wvs);
    gemm_proj_bf<<<dim3(16,64), 256>>>();
    gemm_vc_tc<<<dim3(4,64), 256, GSMEM>>>();
    gemm_vs_tc<<<64, 256, GSMEM>>>();
    repack_v<<<dim3(8,16), 256>>>();
    vcs_reduce<<<1, 256>>>();
    flash_mma<<<dim3(32,16), 256, FSMEM>>>(t2, out);
    ca_scores<<<dim3(16,16), 256>>>();
    ca_reduce<<<16, 64>>>(t1);
    ca_out<<<dim3(64,16), 256>>>(out);
}